// round 1
// baseline (speedup 1.0000x reference)
#include <cuda_runtime.h>
#include <math.h>

#define NN 16384          // nodes per type
#define HIDDIM 256        // hidden
#define NHD 8             // heads
#define DD 32             // head dim
#define NE 65536          // edges per edge type
#define NT 3              // node types
#define NRR 4             // edge types
#define NLL 4             // layers
#define NXH (NN*HIDDIM)

// ---------------- device scratch (allocation-free) ----------------
__device__ float g_h[NT*NXH];
__device__ float g_k[NT*NXH];
__device__ float g_q[NT*NXH];
__device__ float g_v[NT*NXH];
__device__ float g_krel[NRR*NXH];
__device__ float g_mrel[NRR*NXH];
__device__ float g_sc[NRR*NE*NHD];
__device__ float g_mx[NT*NN*NHD];
__device__ float g_den[NT*NN*NHD];
__device__ float g_agg[NT*NXH];
__device__ float g_pre[NT*NXH];

// buffer ids
#define ID_H 0
#define ID_K 1
#define ID_Q 2
#define ID_V 3
#define ID_KREL 4
#define ID_MREL 5
#define ID_SC 6
#define ID_MX 7
#define ID_DEN 8
#define ID_AGG 9
#define ID_PRE 10

__device__ __forceinline__ float* devbuf(int id) {
  switch (id) {
    case ID_H: return g_h; case ID_K: return g_k; case ID_Q: return g_q; case ID_V: return g_v;
    case ID_KREL: return g_krel; case ID_MREL: return g_mrel; case ID_SC: return g_sc;
    case ID_MX: return g_mx; case ID_DEN: return g_den; case ID_AGG: return g_agg;
    default: return g_pre;
  }
}

__device__ __forceinline__ float gelu_t(float x) {
  float x3 = x*x*x;
  return 0.5f*x*(1.0f + tanhf(0.7978845608028654f*(x + 0.044715f*x3)));
}

// ---------------- GEMM: C[16384,256] = act(A)[16384,256] @ W[256,256] + bias ----------------
// 64x64 tile, BK=16, 256 threads, 4x4 per thread, fp32.
template<int ACT>
__global__ void __launch_bounds__(256) gemm256(
    const float* __restrict__ Ae, int Ai, long long Ao,
    const float* __restrict__ W, const float* __restrict__ bias,
    float* __restrict__ Ce, int Ci, long long Co)
{
  const float* A = Ae ? Ae : (const float*)(devbuf(Ai) + Ao);
  float* C = Ce ? Ce : (devbuf(Ci) + Co);

  __shared__ float As[16][64];
  __shared__ float Bs[16][64];
  int tid = threadIdx.x;
  int tx = tid & 15, ty = tid >> 4;
  int arow = tid >> 2, acol4 = (tid & 3) << 2;   // A tile load: 64 rows x 16 k
  int brow = tid >> 4, bcol4 = (tid & 15) << 2;  // B tile load: 16 k x 64 cols

  const float* Ap = A + (size_t)(blockIdx.y*64 + arow)*HIDDIM;
  const float* Wp = W + blockIdx.x*64;
  float acc[4][4] = {};

  for (int k0 = 0; k0 < HIDDIM; k0 += 16) {
    float4 av = *(const float4*)(Ap + k0 + acol4);
    if (ACT) { av.x=gelu_t(av.x); av.y=gelu_t(av.y); av.z=gelu_t(av.z); av.w=gelu_t(av.w); }
    As[acol4+0][arow]=av.x; As[acol4+1][arow]=av.y; As[acol4+2][arow]=av.z; As[acol4+3][arow]=av.w;
    *(float4*)&Bs[brow][bcol4] = *(const float4*)(Wp + (size_t)(k0+brow)*HIDDIM + bcol4);
    __syncthreads();
    #pragma unroll
    for (int kk=0; kk<16; kk++) {
      float a0=As[kk][ty*4+0], a1=As[kk][ty*4+1], a2=As[kk][ty*4+2], a3=As[kk][ty*4+3];
      float4 b = *(const float4*)&Bs[kk][tx*4];
      acc[0][0]+=a0*b.x; acc[0][1]+=a0*b.y; acc[0][2]+=a0*b.z; acc[0][3]+=a0*b.w;
      acc[1][0]+=a1*b.x; acc[1][1]+=a1*b.y; acc[1][2]+=a1*b.z; acc[1][3]+=a1*b.w;
      acc[2][0]+=a2*b.x; acc[2][1]+=a2*b.y; acc[2][2]+=a2*b.z; acc[2][3]+=a2*b.w;
      acc[3][0]+=a3*b.x; acc[3][1]+=a3*b.y; acc[3][2]+=a3*b.z; acc[3][3]+=a3*b.w;
    }
    __syncthreads();
  }
  int col = blockIdx.x*64 + tx*4;
  float4 bb = *(const float4*)(bias + col);
  #pragma unroll
  for (int i=0;i<4;i++) {
    int row = blockIdx.y*64 + ty*4 + i;
    float4 o;
    o.x=acc[i][0]+bb.x; o.y=acc[i][1]+bb.y; o.z=acc[i][2]+bb.z; o.w=acc[i][3]+bb.w;
    *(float4*)(C + (size_t)row*HIDDIM + col) = o;
  }
}

// ---------------- per-head relation transform: out[n, h*32+e] = sum_d X[n, h*32+d]*Wrel[h,d,e] ----------------
__global__ void __launch_bounds__(256) rel_transform(
    int xv /*0:k 1:v*/, long long xoff, const float* __restrict__ Wrel,
    int om /*0:krel 1:mrel*/, long long ooff)
{
  const float* X = (xv ? g_v : g_k) + xoff;
  float* O = (om ? g_mrel : g_krel) + ooff;
  __shared__ float Wm[32][32];
  __shared__ float Xs[64][32];
  int h = blockIdx.y, tid = threadIdx.x;
  for (int i = tid; i < 1024; i += 256) Wm[i>>5][i&31] = Wrel[(h<<10) + i];
  int r0 = blockIdx.x * 64;
  for (int i = tid; i < 2048; i += 256) {
    int rr = i >> 5, cc = i & 31;
    Xs[rr][cc] = X[(size_t)(r0+rr)*HIDDIM + (h<<5) + cc];
  }
  __syncthreads();
  int e = tid & 31, rg = tid >> 5;
  for (int rr = rg; rr < 64; rr += 8) {
    float acc = 0.f;
    #pragma unroll
    for (int d=0; d<32; d++) acc += Xs[rr][d]*Wm[d][e];
    O[(size_t)(r0+rr)*HIDDIM + (h<<5) + e] = acc;
  }
}

// ---------------- fill ----------------
__global__ void fillk(int id, long long off, float v, long long n) {
  float* p = devbuf(id) + off;
  long long i = (long long)blockIdx.x*blockDim.x + threadIdx.x;
  long long stride = (long long)gridDim.x*blockDim.x;
  for (; i < n; i += stride) p[i] = v;
}

// ---------------- edge score + segment max ----------------
__device__ __forceinline__ void atomicMaxF(float* addr, float val) {
  int* ia = (int*)addr;
  int old = *ia;
  while (__int_as_float(old) < val) {
    int assumed = old;
    old = atomicCAS(ia, assumed, __float_as_int(val));
    if (old == assumed) break;
  }
}

__global__ void __launch_bounds__(256) score_pass(
    long long qoff, long long kroff, const int* __restrict__ ei,
    const float* __restrict__ prel, long long scoff, long long mxoff)
{
  int e = blockIdx.x*8 + (threadIdx.x >> 5);
  int lane = threadIdx.x & 31;
  int src = ei[e], dst = ei[NE + e];
  const float* qr = g_q + qoff + (size_t)dst*HIDDIM;
  const float* kr = g_krel + kroff + (size_t)src*HIDDIM;
  float myS = 0.f;
  #pragma unroll
  for (int hh=0; hh<8; hh++) {
    float p = qr[hh*32+lane]*kr[hh*32+lane];
    #pragma unroll
    for (int o=16;o;o>>=1) p += __shfl_xor_sync(0xffffffffu, p, o);
    if (lane == hh) myS = p;
  }
  if (lane < 8) {
    float s = myS * prel[lane] * 0.17677669529663687f;  // 1/sqrt(32)
    g_sc[scoff + (size_t)e*8 + lane] = s;
    atomicMaxF(&g_mx[mxoff + (size_t)dst*8 + lane], s);
  }
}

// ---------------- exp + segment sum ----------------
__global__ void __launch_bounds__(256) expden_pass(const int* __restrict__ ei,
    long long mxoff, long long scoff, long long denoff)
{
  int idx = blockIdx.x*256 + threadIdx.x;   // NE*8 total
  int e = idx >> 3, hh = idx & 7;
  int dst = ei[NE + e];
  float ex = expf(g_sc[scoff + idx] - g_mx[mxoff + (size_t)dst*8 + hh]);
  g_sc[scoff + idx] = ex;
  atomicAdd(&g_den[denoff + (size_t)dst*8 + hh], ex);
}

// ---------------- weighted message aggregation (vector red) ----------------
__global__ void __launch_bounds__(256) agg_pass(const int* __restrict__ ei,
    long long mroff, long long scoff, long long denoff, long long aggoff)
{
  int e = blockIdx.x*8 + (threadIdx.x >> 5);
  int lane = threadIdx.x & 31;
  int src = ei[e], dst = ei[NE + e];
  float alpha = 0.f;
  if (lane < 8) {
    float ex = g_sc[scoff + (size_t)e*8 + lane];
    float dn = g_den[denoff + (size_t)dst*8 + lane];
    alpha = ex / fmaxf(dn, 1e-16f);
  }
  const float4* mr = (const float4*)(g_mrel + mroff + (size_t)src*HIDDIM);
  float4* ag = (float4*)(g_agg + aggoff + (size_t)dst*HIDDIM);
  #pragma unroll
  for (int it=0; it<2; it++) {
    int f4 = it*32 + lane;                    // 64 float4 = 256 floats
    float a = __shfl_sync(0xffffffffu, alpha, f4 >> 3);
    float4 mv = mr[f4];
    asm volatile("red.global.add.v4.f32 [%0], {%1,%2,%3,%4};"
                 :: "l"(ag + f4), "f"(mv.x*a), "f"(mv.y*a), "f"(mv.z*a), "f"(mv.w*a)
                 : "memory");
  }
}

// ---------------- gated skip + residual + LayerNorm (in-place on g_h) ----------------
__global__ void __launch_bounds__(256) skip_ln(
    long long preoff, long long hoff, const float* __restrict__ g,
    const float* __restrict__ bb, const float* __restrict__ skipv)
{
  int row = blockIdx.x, c = threadIdx.x;
  float a = 1.f/(1.f + expf(-skipv[0]));
  size_t idx = (size_t)row*HIDDIM + c;
  float p = g_pre[preoff + idx];
  float hh = g_h[hoff + idx];
  float y = a*p + (1.f - a)*hh + hh;   // conv + residual
  __shared__ float s1[8], s2[8];
  float v1=y, v2=y*y;
  #pragma unroll
  for (int o=16;o;o>>=1){ v1+=__shfl_xor_sync(0xffffffffu,v1,o); v2+=__shfl_xor_sync(0xffffffffu,v2,o); }
  if ((c&31)==0){ s1[c>>5]=v1; s2[c>>5]=v2; }
  __syncthreads();
  float sum=0.f, sq=0.f;
  #pragma unroll
  for (int i=0;i<8;i++){ sum+=s1[i]; sq+=s2[i]; }
  float mu = sum*(1.f/256.f);
  float var = sq*(1.f/256.f) - mu*mu;
  float o = (y - mu)*rsqrtf(var + 1e-5f)*g[c] + bb[c];
  g_h[hoff + idx] = o;
}

// ---------------- host orchestration ----------------
extern "C" void kernel_launch(void* const* d_in, const int* in_sizes, int n_in,
                              void* d_out, int out_size) {
  const float* x[NT]  = {(const float*)d_in[0], (const float*)d_in[1], (const float*)d_in[2]};
  const int*   ei[NRR]= {(const int*)d_in[3], (const int*)d_in[4], (const int*)d_in[5], (const int*)d_in[6]};
  const float* Win   = (const float*)d_in[7];
  const float* b_in  = (const float*)d_in[8];
  const float* Kw    = (const float*)d_in[9];
  const float* Kb    = (const float*)d_in[10];
  const float* Qw    = (const float*)d_in[11];
  const float* Qb    = (const float*)d_in[12];
  const float* Vw    = (const float*)d_in[13];
  const float* Vb    = (const float*)d_in[14];
  const float* Arel  = (const float*)d_in[15];
  const float* Mrel  = (const float*)d_in[16];
  const float* Prel  = (const float*)d_in[17];
  const float* Aw    = (const float*)d_in[18];
  const float* Ab    = (const float*)d_in[19];
  const float* skip  = (const float*)d_in[20];
  const float* ln_g  = (const float*)d_in[21];
  const float* ln_b  = (const float*)d_in[22];
  const float* Wout  = (const float*)d_in[23];
  const float* b_out = (const float*)d_in[24];
  float* out = (float*)d_out;

  static const int RSRC[NRR] = {1, 0, 2, 0};
  static const int RDST[NRR] = {0, 2, 1, 0};

  dim3 gg(4, 256);   // (n tiles, m tiles)

  // input projections
  for (int t = 0; t < NT; t++)
    gemm256<0><<<gg,256>>>(x[t], -1, 0, Win + (size_t)t*65536, b_in + t*HIDDIM,
                           nullptr, ID_H, (long long)t*NXH);

  for (int l = 0; l < NLL; l++) {
    // K/Q/V projections
    for (int t = 0; t < NT; t++) {
      long long wi = (long long)(l*NT + t);
      gemm256<0><<<gg,256>>>(nullptr, ID_H, (long long)t*NXH, Kw + wi*65536, Kb + wi*HIDDIM,
                             nullptr, ID_K, (long long)t*NXH);
      gemm256<0><<<gg,256>>>(nullptr, ID_H, (long long)t*NXH, Qw + wi*65536, Qb + wi*HIDDIM,
                             nullptr, ID_Q, (long long)t*NXH);
      gemm256<0><<<gg,256>>>(nullptr, ID_H, (long long)t*NXH, Vw + wi*65536, Vb + wi*HIDDIM,
                             nullptr, ID_V, (long long)t*NXH);
    }
    // relation-specific key/message transforms
    for (int r = 0; r < NRR; r++) {
      long long ri = (long long)(l*NRR + r);
      rel_transform<<<dim3(NN/64, NHD),256>>>(0, (long long)RSRC[r]*NXH, Arel + ri*(NHD*DD*DD),
                                              0, (long long)r*NXH);
      rel_transform<<<dim3(NN/64, NHD),256>>>(1, (long long)RSRC[r]*NXH, Mrel + ri*(NHD*DD*DD),
                                              1, (long long)r*NXH);
    }
    // reset segment buffers
    fillk<<<1536,256>>>(ID_MX, 0, -INFINITY, (long long)NT*NN*NHD);
    fillk<<<1536,256>>>(ID_DEN, 0, 0.f, (long long)NT*NN*NHD);
    fillk<<<49152,256>>>(ID_AGG, 0, 0.f, (long long)NT*NXH);
    // scores + segment max
    for (int r = 0; r < NRR; r++)
      score_pass<<<NE/8,256>>>((long long)RDST[r]*NXH, (long long)r*NXH, ei[r],
                               Prel + (size_t)(l*NRR + r)*NHD,
                               (long long)r*NE*NHD, (long long)RDST[r]*NN*NHD);
    // exp + segment sum
    for (int r = 0; r < NRR; r++)
      expden_pass<<<(NE*NHD)/256,256>>>(ei[r], (long long)RDST[r]*NN*NHD,
                                        (long long)r*NE*NHD, (long long)RDST[r]*NN*NHD);
    // weighted aggregation
    for (int r = 0; r < NRR; r++)
      agg_pass<<<NE/8,256>>>(ei[r], (long long)r*NXH, (long long)r*NE*NHD,
                             (long long)RDST[r]*NN*NHD, (long long)RDST[r]*NXH);
    // gelu -> A linear -> gated skip + residual + LN
    for (int t = 0; t < NT; t++) {
      long long wi = (long long)(l*NT + t);
      gemm256<1><<<gg,256>>>(nullptr, ID_AGG, (long long)t*NXH, Aw + wi*65536, Ab + wi*HIDDIM,
                             nullptr, ID_PRE, (long long)t*NXH);
      skip_ln<<<NN,256>>>((long long)t*NXH, (long long)t*NXH,
                          ln_g + wi*HIDDIM, ln_b + wi*HIDDIM, skip + wi);
    }
  }

  // output projections
  for (int t = 0; t < NT; t++)
    gemm256<0><<<gg,256>>>(nullptr, ID_H, (long long)t*NXH, Wout + (size_t)t*65536, b_out + t*HIDDIM,
                           out + (size_t)t*NXH, -1, 0);
}

// round 3
// speedup vs baseline: 2.2106x; 2.2106x over previous
#include <cuda_runtime.h>
#include <math.h>
#include <stdint.h>

#define NN 16384
#define HIDDIM 256
#define NHD 8
#define DD 32
#define NE 65536
#define NT 3
#define NRR 4
#define NLL 4
#define NXH (NN*HIDDIM)

// ---------------- device scratch (allocation-free) ----------------
__device__ float g_h[NT*NXH];
__device__ float g_q[NT*NXH];
__device__ float g_krel[NRR*NXH];
__device__ float g_mrel[NRR*NXH];
__device__ float g_sc[NRR*NE*NHD];
__device__ float g_mx[NT*NN*NHD];
__device__ float g_den[NT*NN*NHD];
__device__ float g_agg[NT*NXH];
__device__ float g_pre[NT*NXH];
__device__ float g_wf[2*NLL*NRR*HIDDIM*HIDDIM];   // folded Krel/Vrel weights
__device__ float g_bf[2*NLL*NRR*HIDDIM];          // folded biases

#define ID_H 0
#define ID_Q 1
#define ID_KREL 2
#define ID_MREL 3
#define ID_SC 4
#define ID_MX 5
#define ID_DEN 6
#define ID_AGG 7
#define ID_PRE 8
#define ID_WF 9
#define ID_BF 10

__device__ __forceinline__ float* devbuf(int id) {
  switch (id) {
    case ID_H: return g_h; case ID_Q: return g_q; case ID_KREL: return g_krel;
    case ID_MREL: return g_mrel; case ID_SC: return g_sc; case ID_MX: return g_mx;
    case ID_DEN: return g_den; case ID_AGG: return g_agg; case ID_PRE: return g_pre;
    case ID_WF: return g_wf; default: return g_bf;
  }
}

__device__ __forceinline__ float gelu_t(float x) {
  float x3 = x*x*x;
  return 0.5f*x*(1.0f + tanhf(0.7978845608028654f*(x + 0.044715f*x3)));
}

__device__ __forceinline__ uint32_t smem_u32(const void* p) {
  uint32_t a;
  asm("{ .reg .u64 t; cvta.to.shared.u64 t, %1; cvt.u32.u64 %0, t; }" : "=r"(a) : "l"(p));
  return a;
}

// ================= tf32 mma.sync GEMM =================
// C[16384,256] = A[16384,256] @ W[256,256] + bias.
// CTA tile 128x128, 8 warps of 32x64, K chunks of 32, cp.async double buffer.
struct GemmJob {
  const float* Aext; int Aid; long long Aoff;
  const float* Wext; int Wid; long long Woff;
  const float* Bext; int Bid; long long Boff;
  float* Cext; int Cid; long long Coff;
};
struct GemmBatch { GemmJob j[12]; };

#define APITCH 36    // floats per A smem row (32 + 4 pad)
#define BPITCH 136   // floats per B smem row (128 + 8 pad)
#define ASZ (128*APITCH)       // 4608 floats per buffer
#define BSZ (32*BPITCH)        // 4352 floats per buffer
#define GEMM_SMEM ((2*ASZ + 2*BSZ)*4)   // 71680 bytes

__device__ __forceinline__ void mma_tf32(float* c, const uint32_t* a, const uint32_t* b) {
  asm volatile(
      "mma.sync.aligned.m16n8k8.row.col.f32.tf32.tf32.f32 "
      "{%0,%1,%2,%3}, {%4,%5,%6,%7}, {%8,%9}, {%0,%1,%2,%3};"
      : "+f"(c[0]), "+f"(c[1]), "+f"(c[2]), "+f"(c[3])
      : "r"(a[0]), "r"(a[1]), "r"(a[2]), "r"(a[3]), "r"(b[0]), "r"(b[1]));
}

__global__ void __launch_bounds__(256, 1) gemm_mma(GemmBatch batch) {
  const GemmJob jb = batch.j[blockIdx.y];
  const float* A = jb.Aext ? jb.Aext : (const float*)(devbuf(jb.Aid) + jb.Aoff);
  const float* W = jb.Wext ? jb.Wext : (const float*)(devbuf(jb.Wid) + jb.Woff);
  const float* bias = jb.Bext ? jb.Bext : (const float*)(devbuf(jb.Bid) + jb.Boff);
  float* C = jb.Cext ? jb.Cext : (devbuf(jb.Cid) + jb.Coff);

  const int m0 = (blockIdx.x >> 1) * 128;
  const int n0 = (blockIdx.x & 1) * 128;

  extern __shared__ float sm[];
  float* AsBase = sm;                  // 2 buffers of ASZ
  float* BsBase = sm + 2*ASZ;          // 2 buffers of BSZ
  const uint32_t sA = smem_u32(AsBase);
  const uint32_t sB = smem_u32(BsBase);

  const int tid = threadIdx.x, lane = tid & 31, wid = tid >> 5;
  const int quad = lane >> 2, tc = lane & 3;
  const int wm = (wid & 3) * 32, wn = (wid >> 2) * 64;

  float acc[2][8][4];
  #pragma unroll
  for (int mt = 0; mt < 2; mt++)
    #pragma unroll
    for (int nt = 0; nt < 8; nt++)
      #pragma unroll
      for (int i = 0; i < 4; i++) acc[mt][nt][i] = 0.f;

  // cp.async issue for one K-chunk into buffer buf
  auto issue = [&](int buf, int k0) {
    #pragma unroll
    for (int j = 0; j < 4; j++) {   // A: 128 rows x 32 floats = 1024 x 16B
      int t2 = tid + j*256;
      int row = t2 >> 3, seg = t2 & 7;
      const float* src = A + (size_t)(m0 + row)*HIDDIM + k0 + seg*4;
      uint32_t dst = sA + (uint32_t)(buf*ASZ + row*APITCH + seg*4)*4u;
      asm volatile("cp.async.cg.shared.global [%0], [%1], 16;" :: "r"(dst), "l"(src) : "memory");
    }
    #pragma unroll
    for (int j = 0; j < 4; j++) {   // B: 32 k-rows x 128 floats = 1024 x 16B
      int t2 = tid + j*256;
      int row = t2 >> 5, seg = t2 & 31;
      const float* src = W + (size_t)(k0 + row)*HIDDIM + n0 + seg*4;
      uint32_t dst = sB + (uint32_t)(buf*BSZ + row*BPITCH + seg*4)*4u;
      asm volatile("cp.async.cg.shared.global [%0], [%1], 16;" :: "r"(dst), "l"(src) : "memory");
    }
    asm volatile("cp.async.commit_group;" ::: "memory");
  };

  issue(0, 0);

  for (int ch = 0; ch < 8; ch++) {
    if (ch < 7) issue((ch + 1) & 1, (ch + 1) * 32);
    if (ch < 7) asm volatile("cp.async.wait_group 1;" ::: "memory");
    else        asm volatile("cp.async.wait_group 0;" ::: "memory");
    __syncthreads();

    const float* Ab = AsBase + (ch & 1)*ASZ;
    const float* Bb = BsBase + (ch & 1)*BSZ;
    #pragma unroll
    for (int kk8 = 0; kk8 < 4; kk8++) {
      const int kk = kk8 * 8;
      uint32_t a[2][4], b[8][2];
      #pragma unroll
      for (int mt = 0; mt < 2; mt++) {
        int r = wm + mt*16 + quad;
        a[mt][0] = __float_as_uint(Ab[r*APITCH + kk + tc]);
        a[mt][1] = __float_as_uint(Ab[(r+8)*APITCH + kk + tc]);
        a[mt][2] = __float_as_uint(Ab[r*APITCH + kk + tc + 4]);
        a[mt][3] = __float_as_uint(Ab[(r+8)*APITCH + kk + tc + 4]);
      }
      #pragma unroll
      for (int nt = 0; nt < 8; nt++) {
        int n = wn + nt*8 + quad;
        b[nt][0] = __float_as_uint(Bb[(kk + tc)*BPITCH + n]);
        b[nt][1] = __float_as_uint(Bb[(kk + tc + 4)*BPITCH + n]);
      }
      #pragma unroll
      for (int mt = 0; mt < 2; mt++)
        #pragma unroll
        for (int nt = 0; nt < 8; nt++)
          mma_tf32(acc[mt][nt], a[mt], b[nt]);
    }
    __syncthreads();
  }

  // epilogue
  #pragma unroll
  for (int nt = 0; nt < 8; nt++) {
    int cix = n0 + wn + nt*8 + tc*2;
    float2 bv = *(const float2*)(bias + cix);
    #pragma unroll
    for (int mt = 0; mt < 2; mt++) {
      int r = m0 + wm + mt*16 + quad;
      float2 o0; o0.x = acc[mt][nt][0] + bv.x; o0.y = acc[mt][nt][1] + bv.y;
      float2 o1; o1.x = acc[mt][nt][2] + bv.x; o1.y = acc[mt][nt][3] + bv.y;
      *(float2*)(C + (size_t)r*HIDDIM + cix) = o0;
      *(float2*)(C + (size_t)(r+8)*HIDDIM + cix) = o1;
    }
  }
}

// ================= fold relation matrices into K/V weights =================
__global__ void __launch_bounds__(256) fold_weights(
    const float* __restrict__ Kw, const float* __restrict__ Kb,
    const float* __restrict__ Vw, const float* __restrict__ Vb,
    const float* __restrict__ Arel, const float* __restrict__ Mrel)
{
  int b = blockIdx.x;
  int r = b & 3, l = (b >> 2) & 3, kv = b >> 4;
  const int RSRC[4] = {1, 0, 2, 0};
  int s = RSRC[r];
  const float* W   = (kv ? Vw : Kw) + (size_t)(l*NT + s)*HIDDIM*HIDDIM;
  const float* bb  = (kv ? Vb : Kb) + (size_t)(l*NT + s)*HIDDIM;
  const float* Rel = (kv ? Mrel : Arel) + (size_t)(l*NRR + r)*NHD*DD*DD;
  float* Wo = g_wf + (size_t)(kv*NLL*NRR + l*NRR + r)*HIDDIM*HIDDIM;
  float* bo = g_bf + (size_t)(kv*NLL*NRR + l*NRR + r)*HIDDIM;

  __shared__ float Rs[NHD*DD*DD];
  int tid = threadIdx.x;
  for (int i = tid; i < NHD*DD*DD; i += 256) Rs[i] = Rel[i];
  __syncthreads();

  const float* wrow = W + (size_t)tid*HIDDIM;
  float* worow = Wo + (size_t)tid*HIDDIM;
  for (int h = 0; h < NHD; h++) {
    float xv[DD];
    #pragma unroll
    for (int d = 0; d < DD; d++) xv[d] = wrow[h*DD + d];
    for (int e = 0; e < DD; e++) {
      float acc = 0.f;
      #pragma unroll
      for (int d = 0; d < DD; d++) acc += xv[d] * Rs[(h*DD + d)*DD + e];
      worow[h*DD + e] = acc;
    }
  }
  {
    int h = tid >> 5, e = tid & 31;
    float acc = 0.f;
    #pragma unroll
    for (int d = 0; d < DD; d++) acc += bb[h*DD + d] * Rs[(h*DD + d)*DD + e];
    bo[tid] = acc;
  }
}

// ================= fill =================
__global__ void fillk(int id, long long off, float v, long long n) {
  float* p = devbuf(id) + off;
  long long i = (long long)blockIdx.x*blockDim.x + threadIdx.x;
  long long stride = (long long)gridDim.x*blockDim.x;
  for (; i < n; i += stride) p[i] = v;
}

// ================= gelu over g_agg =================
__global__ void gelu_pass() {
  long long n = (long long)NT*NXH;
  long long i = (long long)blockIdx.x*blockDim.x + threadIdx.x;
  long long stride = (long long)gridDim.x*blockDim.x;
  for (; i < n; i += stride) g_agg[i] = gelu_t(g_agg[i]);
}

// ================= edge score + segment max =================
__device__ __forceinline__ void atomicMaxF(float* addr, float val) {
  int* ia = (int*)addr;
  int old = *ia;
  while (__int_as_float(old) < val) {
    int assumed = old;
    old = atomicCAS(ia, assumed, __float_as_int(val));
    if (old == assumed) break;
  }
}

__global__ void __launch_bounds__(256) score_pass(
    long long qoff, long long kroff, const int* __restrict__ ei,
    const float* __restrict__ prel, long long scoff, long long mxoff)
{
  int e = blockIdx.x*8 + (threadIdx.x >> 5);
  int lane = threadIdx.x & 31;
  int src = ei[e], dst = ei[NE + e];
  const float* qr = g_q + qoff + (size_t)dst*HIDDIM;
  const float* kr = g_krel + kroff + (size_t)src*HIDDIM;
  float myS = 0.f;
  #pragma unroll
  for (int hh = 0; hh < 8; hh++) {
    float p = qr[hh*32+lane]*kr[hh*32+lane];
    #pragma unroll
    for (int o = 16; o; o >>= 1) p += __shfl_xor_sync(0xffffffffu, p, o);
    if (lane == hh) myS = p;
  }
  if (lane < 8) {
    float s = myS * prel[lane] * 0.17677669529663687f;
    g_sc[scoff + (size_t)e*8 + lane] = s;
    atomicMaxF(&g_mx[mxoff + (size_t)dst*8 + lane], s);
  }
}

// ================= exp + segment sum =================
__global__ void __launch_bounds__(256) expden_pass(const int* __restrict__ ei,
    long long mxoff, long long scoff, long long denoff)
{
  int idx = blockIdx.x*256 + threadIdx.x;
  int e = idx >> 3, hh = idx & 7;
  int dst = ei[NE + e];
  float ex = expf(g_sc[scoff + idx] - g_mx[mxoff + (size_t)dst*8 + hh]);
  g_sc[scoff + idx] = ex;
  atomicAdd(&g_den[denoff + (size_t)dst*8 + hh], ex);
}

// ================= weighted message aggregation =================
__global__ void __launch_bounds__(256) agg_pass(const int* __restrict__ ei,
    long long mroff, long long scoff, long long denoff, long long aggoff)
{
  int e = blockIdx.x*8 + (threadIdx.x >> 5);
  int lane = threadIdx.x & 31;
  int src = ei[e], dst = ei[NE + e];
  float alpha = 0.f;
  if (lane < 8) {
    float ex = g_sc[scoff + (size_t)e*8 + lane];
    float dn = g_den[denoff + (size_t)dst*8 + lane];
    alpha = ex / fmaxf(dn, 1e-16f);
  }
  const float4* mr = (const float4*)(g_mrel + mroff + (size_t)src*HIDDIM);
  float4* ag = (float4*)(g_agg + aggoff + (size_t)dst*HIDDIM);
  #pragma unroll
  for (int it = 0; it < 2; it++) {
    int f4 = it*32 + lane;
    float a = __shfl_sync(0xffffffffu, alpha, f4 >> 3);
    float4 mv = mr[f4];
    asm volatile("red.global.add.v4.f32 [%0], {%1,%2,%3,%4};"
                 :: "l"(ag + f4), "f"(mv.x*a), "f"(mv.y*a), "f"(mv.z*a), "f"(mv.w*a)
                 : "memory");
  }
}

// ================= gated skip + residual + LayerNorm =================
__global__ void __launch_bounds__(256) skip_ln(
    long long preoff, long long hoff, const float* __restrict__ g,
    const float* __restrict__ bb, const float* __restrict__ skipv)
{
  int row = blockIdx.x, c = threadIdx.x;
  float a = 1.f/(1.f + expf(-skipv[0]));
  size_t idx = (size_t)row*HIDDIM + c;
  float p = g_pre[preoff + idx];
  float hh = g_h[hoff + idx];
  float y = a*p + (1.f - a)*hh + hh;
  __shared__ float s1[8], s2[8];
  float v1 = y, v2 = y*y;
  #pragma unroll
  for (int o = 16; o; o >>= 1) {
    v1 += __shfl_xor_sync(0xffffffffu, v1, o);
    v2 += __shfl_xor_sync(0xffffffffu, v2, o);
  }
  if ((c & 31) == 0) { s1[c>>5] = v1; s2[c>>5] = v2; }
  __syncthreads();
  float sum = 0.f, sq = 0.f;
  #pragma unroll
  for (int i = 0; i < 8; i++) { sum += s1[i]; sq += s2[i]; }
  float mu = sum*(1.f/256.f);
  float var = sq*(1.f/256.f) - mu*mu;
  float o = (y - mu)*rsqrtf(var + 1e-5f)*g[c] + bb[c];
  g_h[hoff + idx] = o;
}

// ================= host orchestration =================
static inline GemmJob JB(const float* Aext, int Aid, long long Aoff,
                         const float* Wext, int Wid, long long Woff,
                         const float* Bext, int Bid, long long Boff,
                         float* Cext, int Cid, long long Coff) {
  GemmJob j; j.Aext=Aext; j.Aid=Aid; j.Aoff=Aoff; j.Wext=Wext; j.Wid=Wid; j.Woff=Woff;
  j.Bext=Bext; j.Bid=Bid; j.Boff=Boff; j.Cext=Cext; j.Cid=Cid; j.Coff=Coff;
  return j;
}

extern "C" void kernel_launch(void* const* d_in, const int* in_sizes, int n_in,
                              void* d_out, int out_size) {
  const float* x[NT]  = {(const float*)d_in[0], (const float*)d_in[1], (const float*)d_in[2]};
  const int*   ei[NRR]= {(const int*)d_in[3], (const int*)d_in[4], (const int*)d_in[5], (const int*)d_in[6]};
  const float* Win   = (const float*)d_in[7];
  const float* b_in  = (const float*)d_in[8];
  const float* Kw    = (const float*)d_in[9];
  const float* Kb    = (const float*)d_in[10];
  const float* Qw    = (const float*)d_in[11];
  const float* Qb    = (const float*)d_in[12];
  const float* Vw    = (const float*)d_in[13];
  const float* Vb    = (const float*)d_in[14];
  const float* Arel  = (const float*)d_in[15];
  const float* Mrel  = (const float*)d_in[16];
  const float* Prel  = (const float*)d_in[17];
  const float* Aw    = (const float*)d_in[18];
  const float* Ab    = (const float*)d_in[19];
  const float* skip  = (const float*)d_in[20];
  const float* ln_g  = (const float*)d_in[21];
  const float* ln_b  = (const float*)d_in[22];
  const float* Wout  = (const float*)d_in[23];
  const float* b_out = (const float*)d_in[24];
  float* out = (float*)d_out;

  static const int RSRC[NRR] = {1, 0, 2, 0};
  static const int RDST[NRR] = {0, 2, 1, 0};

  cudaFuncSetAttribute(gemm_mma, cudaFuncAttributeMaxDynamicSharedMemorySize, GEMM_SMEM);

  // fold relation matrices into K/V weights + biases
  fold_weights<<<32, 256>>>(Kw, Kb, Vw, Vb, Arel, Mrel);

  // input projections
  {
    GemmBatch b = {};
    for (int t = 0; t < NT; t++)
      b.j[t] = JB(x[t], -1, 0, Win + (size_t)t*65536, -1, 0, b_in + t*HIDDIM, -1, 0,
                  nullptr, ID_H, (long long)t*NXH);
    gemm_mma<<<dim3(256, 3), 256, GEMM_SMEM>>>(b);
  }

  for (int l = 0; l < NLL; l++) {
    // Q (3) + Krel (4) + Vrel (4) in one batched launch
    {
      GemmBatch b = {};
      int n = 0;
      for (int t = 0; t < NT; t++) {
        long long wi = (long long)(l*NT + t);
        b.j[n++] = JB(nullptr, ID_H, (long long)t*NXH, Qw + wi*65536, -1, 0,
                      Qb + wi*HIDDIM, -1, 0, nullptr, ID_Q, (long long)t*NXH);
      }
      for (int r = 0; r < NRR; r++) {
        long long fo = (long long)(l*NRR + r);
        b.j[n++] = JB(nullptr, ID_H, (long long)RSRC[r]*NXH, nullptr, ID_WF, fo*65536,
                      nullptr, ID_BF, fo*HIDDIM, nullptr, ID_KREL, (long long)r*NXH);
      }
      for (int r = 0; r < NRR; r++) {
        long long fo = (long long)(NLL*NRR + l*NRR + r);
        b.j[n++] = JB(nullptr, ID_H, (long long)RSRC[r]*NXH, nullptr, ID_WF, fo*65536,
                      nullptr, ID_BF, fo*HIDDIM, nullptr, ID_MREL, (long long)r*NXH);
      }
      gemm_mma<<<dim3(256, 11), 256, GEMM_SMEM>>>(b);
    }
    // reset segment buffers
    fillk<<<1536, 256>>>(ID_MX, 0, -INFINITY, (long long)NT*NN*NHD);
    fillk<<<1536, 256>>>(ID_DEN, 0, 0.f, (long long)NT*NN*NHD);
    fillk<<<49152, 256>>>(ID_AGG, 0, 0.f, (long long)NT*NXH);
    // scores + segment max
    for (int r = 0; r < NRR; r++)
      score_pass<<<NE/8, 256>>>((long long)RDST[r]*NXH, (long long)r*NXH, ei[r],
                                Prel + (size_t)(l*NRR + r)*NHD,
                                (long long)r*NE*NHD, (long long)RDST[r]*NN*NHD);
    // exp + segment sum
    for (int r = 0; r < NRR; r++)
      expden_pass<<<(NE*NHD)/256, 256>>>(ei[r], (long long)RDST[r]*NN*NHD,
                                         (long long)r*NE*NHD, (long long)RDST[r]*NN*NHD);
    // weighted aggregation
    for (int r = 0; r < NRR; r++)
      agg_pass<<<NE/8, 256>>>(ei[r], (long long)r*NXH, (long long)r*NE*NHD,
                              (long long)RDST[r]*NN*NHD, (long long)RDST[r]*NXH);
    // gelu on agg, then A linear, then skip+LN
    gelu_pass<<<4096, 256>>>();
    {
      GemmBatch b = {};
      for (int t = 0; t < NT; t++) {
        long long wi = (long long)(l*NT + t);
        b.j[t] = JB(nullptr, ID_AGG, (long long)t*NXH, Aw + wi*65536, -1, 0,
                    Ab + wi*HIDDIM, -1, 0, nullptr, ID_PRE, (long long)t*NXH);
      }
      gemm_mma<<<dim3(256, 3), 256, GEMM_SMEM>>>(b);
    }
    for (int t = 0; t < NT; t++) {
      long long wi = (long long)(l*NT + t);
      skip_ln<<<NN, 256>>>((long long)t*NXH, (long long)t*NXH,
                           ln_g + wi*HIDDIM, ln_b + wi*HIDDIM, skip + wi);
    }
  }

  // output projections
  {
    GemmBatch b = {};
    for (int t = 0; t < NT; t++)
      b.j[t] = JB(nullptr, ID_H, (long long)t*NXH, Wout + (size_t)t*65536, -1, 0,
                  b_out + t*HIDDIM, -1, 0, out + (size_t)t*NXH, -1, 0);
    gemm_mma<<<dim3(256, 3), 256, GEMM_SMEM>>>(b);
  }
}

// round 4
// speedup vs baseline: 3.1514x; 1.4256x over previous
#include <cuda_runtime.h>
#include <math.h>
#include <stdint.h>

#define NN 16384
#define HIDDIM 256
#define NHD 8
#define DD 32
#define NE 65536
#define NT 3
#define NRR 4
#define NLL 4
#define NXH (NN*HIDDIM)
#define TOTSEG (NT*NN)        // 49152 destination slots
#define TOTEDGE (NRR*NE)      // 262144 edges
#define MAXDEG 128

// ---------------- device scratch (allocation-free) ----------------
__device__ float g_h[NT*NXH];
__device__ float g_q[NT*NXH];
__device__ float g_krel[NRR*NXH];
__device__ float g_mrel[NRR*NXH];
__device__ float g_agg[NT*NXH];
__device__ float g_pre[NT*NXH];
__device__ float g_wf[2*NLL*NRR*HIDDIM*HIDDIM];
__device__ float g_bf[2*NLL*NRR*HIDDIM];
// CSR
__device__ int g_cnt[TOTSEG];
__device__ int g_off[TOTSEG+1];
__device__ int g_pos[TOTSEG];
__device__ int g_bsum[256];
__device__ int g_elist[TOTEDGE];

#define ID_H 0
#define ID_Q 1
#define ID_KREL 2
#define ID_MREL 3
#define ID_AGG 4
#define ID_PRE 5
#define ID_WF 6
#define ID_BF 7

__device__ __forceinline__ float* devbuf(int id) {
  switch (id) {
    case ID_H: return g_h; case ID_Q: return g_q; case ID_KREL: return g_krel;
    case ID_MREL: return g_mrel; case ID_AGG: return g_agg; case ID_PRE: return g_pre;
    case ID_WF: return g_wf; default: return g_bf;
  }
}

__device__ __forceinline__ float gelu_t(float x) {
  float x3 = x*x*x;
  return 0.5f*x*(1.0f + tanhf(0.7978845608028654f*(x + 0.044715f*x3)));
}

__device__ __forceinline__ uint32_t smem_u32(const void* p) {
  uint32_t a;
  asm("{ .reg .u64 t; cvta.to.shared.u64 t, %1; cvt.u32.u64 %0, t; }" : "=r"(a) : "l"(p));
  return a;
}
__device__ __forceinline__ uint32_t f2tf(float f) {
  uint32_t r; asm("cvt.rna.tf32.f32 %0, %1;" : "=r"(r) : "f"(f)); return r;
}

// ================= tf32 mma.sync GEMM (RN-converted fragments) =================
struct GemmJob {
  const float* Aext; int Aid; long long Aoff;
  const float* Wext; int Wid; long long Woff;
  const float* Bext; int Bid; long long Boff;
  float* Cext; int Cid; long long Coff;
};
struct GemmBatch { GemmJob j[12]; };

#define APITCH 36
#define BPITCH 136
#define ASZ (128*APITCH)
#define BSZ (32*BPITCH)
#define GEMM_SMEM ((2*ASZ + 2*BSZ)*4)

__device__ __forceinline__ void mma_tf32(float* c, const uint32_t* a, const uint32_t* b) {
  asm volatile(
      "mma.sync.aligned.m16n8k8.row.col.f32.tf32.tf32.f32 "
      "{%0,%1,%2,%3}, {%4,%5,%6,%7}, {%8,%9}, {%0,%1,%2,%3};"
      : "+f"(c[0]), "+f"(c[1]), "+f"(c[2]), "+f"(c[3])
      : "r"(a[0]), "r"(a[1]), "r"(a[2]), "r"(a[3]), "r"(b[0]), "r"(b[1]));
}

__global__ void __launch_bounds__(256, 1) gemm_mma(GemmBatch batch) {
  const GemmJob jb = batch.j[blockIdx.y];
  const float* A = jb.Aext ? jb.Aext : (const float*)(devbuf(jb.Aid) + jb.Aoff);
  const float* W = jb.Wext ? jb.Wext : (const float*)(devbuf(jb.Wid) + jb.Woff);
  const float* bias = jb.Bext ? jb.Bext : (const float*)(devbuf(jb.Bid) + jb.Boff);
  float* C = jb.Cext ? jb.Cext : (devbuf(jb.Cid) + jb.Coff);

  const int m0 = (blockIdx.x >> 1) * 128;
  const int n0 = (blockIdx.x & 1) * 128;

  extern __shared__ float sm[];
  float* AsBase = sm;
  float* BsBase = sm + 2*ASZ;
  const uint32_t sA = smem_u32(AsBase);
  const uint32_t sB = smem_u32(BsBase);

  const int tid = threadIdx.x, lane = tid & 31, wid = tid >> 5;
  const int quad = lane >> 2, tc = lane & 3;
  const int wm = (wid & 3) * 32, wn = (wid >> 2) * 64;

  float acc[2][8][4];
  #pragma unroll
  for (int mt = 0; mt < 2; mt++)
    #pragma unroll
    for (int nt = 0; nt < 8; nt++)
      #pragma unroll
      for (int i = 0; i < 4; i++) acc[mt][nt][i] = 0.f;

  auto issue = [&](int buf, int k0) {
    #pragma unroll
    for (int j = 0; j < 4; j++) {
      int t2 = tid + j*256;
      int row = t2 >> 3, seg = t2 & 7;
      const float* src = A + (size_t)(m0 + row)*HIDDIM + k0 + seg*4;
      uint32_t dst = sA + (uint32_t)(buf*ASZ + row*APITCH + seg*4)*4u;
      asm volatile("cp.async.cg.shared.global [%0], [%1], 16;" :: "r"(dst), "l"(src) : "memory");
    }
    #pragma unroll
    for (int j = 0; j < 4; j++) {
      int t2 = tid + j*256;
      int row = t2 >> 5, seg = t2 & 31;
      const float* src = W + (size_t)(k0 + row)*HIDDIM + n0 + seg*4;
      uint32_t dst = sB + (uint32_t)(buf*BSZ + row*BPITCH + seg*4)*4u;
      asm volatile("cp.async.cg.shared.global [%0], [%1], 16;" :: "r"(dst), "l"(src) : "memory");
    }
    asm volatile("cp.async.commit_group;" ::: "memory");
  };

  issue(0, 0);

  for (int ch = 0; ch < 8; ch++) {
    if (ch < 7) issue((ch + 1) & 1, (ch + 1) * 32);
    if (ch < 7) asm volatile("cp.async.wait_group 1;" ::: "memory");
    else        asm volatile("cp.async.wait_group 0;" ::: "memory");
    __syncthreads();

    const float* Ab = AsBase + (ch & 1)*ASZ;
    const float* Bb = BsBase + (ch & 1)*BSZ;
    #pragma unroll
    for (int kk8 = 0; kk8 < 4; kk8++) {
      const int kk = kk8 * 8;
      uint32_t a[2][4], b[8][2];
      #pragma unroll
      for (int mt = 0; mt < 2; mt++) {
        int r = wm + mt*16 + quad;
        a[mt][0] = f2tf(Ab[r*APITCH + kk + tc]);
        a[mt][1] = f2tf(Ab[(r+8)*APITCH + kk + tc]);
        a[mt][2] = f2tf(Ab[r*APITCH + kk + tc + 4]);
        a[mt][3] = f2tf(Ab[(r+8)*APITCH + kk + tc + 4]);
      }
      #pragma unroll
      for (int nt = 0; nt < 8; nt++) {
        int n = wn + nt*8 + quad;
        b[nt][0] = f2tf(Bb[(kk + tc)*BPITCH + n]);
        b[nt][1] = f2tf(Bb[(kk + tc + 4)*BPITCH + n]);
      }
      #pragma unroll
      for (int mt = 0; mt < 2; mt++)
        #pragma unroll
        for (int nt = 0; nt < 8; nt++)
          mma_tf32(acc[mt][nt], a[mt], b[nt]);
    }
    __syncthreads();
  }

  #pragma unroll
  for (int nt = 0; nt < 8; nt++) {
    int cix = n0 + wn + nt*8 + tc*2;
    float2 bv = *(const float2*)(bias + cix);
    #pragma unroll
    for (int mt = 0; mt < 2; mt++) {
      int r = m0 + wm + mt*16 + quad;
      float2 o0; o0.x = acc[mt][nt][0] + bv.x; o0.y = acc[mt][nt][1] + bv.y;
      float2 o1; o1.x = acc[mt][nt][2] + bv.x; o1.y = acc[mt][nt][3] + bv.y;
      *(float2*)(C + (size_t)r*HIDDIM + cix) = o0;
      *(float2*)(C + (size_t)(r+8)*HIDDIM + cix) = o1;
    }
  }
}

// ================= fold relation matrices into K/V weights =================
__global__ void __launch_bounds__(256) fold_weights(
    const float* __restrict__ Kw, const float* __restrict__ Kb,
    const float* __restrict__ Vw, const float* __restrict__ Vb,
    const float* __restrict__ Arel, const float* __restrict__ Mrel)
{
  int b = blockIdx.x;
  int r = b & 3, l = (b >> 2) & 3, kv = b >> 4;
  const int RSRC[4] = {1, 0, 2, 0};
  int s = RSRC[r];
  const float* W   = (kv ? Vw : Kw) + (size_t)(l*NT + s)*HIDDIM*HIDDIM;
  const float* bb  = (kv ? Vb : Kb) + (size_t)(l*NT + s)*HIDDIM;
  const float* Rel = (kv ? Mrel : Arel) + (size_t)(l*NRR + r)*NHD*DD*DD;
  float* Wo = g_wf + (size_t)(kv*NLL*NRR + l*NRR + r)*HIDDIM*HIDDIM;
  float* bo = g_bf + (size_t)(kv*NLL*NRR + l*NRR + r)*HIDDIM;

  __shared__ float Rs[NHD*DD*DD];
  int tid = threadIdx.x;
  for (int i = tid; i < NHD*DD*DD; i += 256) Rs[i] = Rel[i];
  __syncthreads();

  const float* wrow = W + (size_t)tid*HIDDIM;
  float* worow = Wo + (size_t)tid*HIDDIM;
  for (int h = 0; h < NHD; h++) {
    float xv[DD];
    #pragma unroll
    for (int d = 0; d < DD; d++) xv[d] = wrow[h*DD + d];
    for (int e = 0; e < DD; e++) {
      float acc = 0.f;
      #pragma unroll
      for (int d = 0; d < DD; d++) acc += xv[d] * Rs[(h*DD + d)*DD + e];
      worow[h*DD + e] = acc;
    }
  }
  {
    int h = tid >> 5, e = tid & 31;
    float acc = 0.f;
    #pragma unroll
    for (int d = 0; d < DD; d++) acc += bb[h*DD + d] * Rs[(h*DD + d)*DD + e];
    bo[tid] = acc;
  }
}

// ================= CSR build (once per call; reused by all 4 layers) =================
__device__ __forceinline__ int rdst_of(int r) { return (r == 1) ? 2 : (r == 2) ? 1 : 0; }

__global__ void csr_zero() {
  int i = blockIdx.x*256 + threadIdx.x;
  if (i < TOTSEG) g_cnt[i] = 0;
}
__global__ void csr_count(const int* __restrict__ e0, const int* __restrict__ e1,
                          const int* __restrict__ e2, const int* __restrict__ e3) {
  int idx = blockIdx.x*256 + threadIdx.x;      // TOTEDGE threads
  int r = idx >> 16, e = idx & 0xFFFF;
  const int* ep = (r == 0) ? e0 : (r == 1) ? e1 : (r == 2) ? e2 : e3;
  int dst = ep[NE + e];
  atomicAdd(&g_cnt[rdst_of(r)*NN + dst], 1);
}
__global__ void csr_scan1() {                   // 192 blocks x 256
  int gid = blockIdx.x*256 + threadIdx.x;
  int v = g_cnt[gid];
  int lane = threadIdx.x & 31, w = threadIdx.x >> 5;
  int x = v;
  #pragma unroll
  for (int o = 1; o < 32; o <<= 1) { int n = __shfl_up_sync(~0u, x, o); if (lane >= o) x += n; }
  __shared__ int ws[8];
  if (lane == 31) ws[w] = x;
  __syncthreads();
  int prefix = 0;
  for (int i = 0; i < w; i++) prefix += ws[i];
  int excl = prefix + x - v;
  g_off[gid] = excl;
  if (threadIdx.x == 255) g_bsum[blockIdx.x] = excl + v;
}
__global__ void csr_scan2() {                   // 1 block x 256 over 192 entries
  int v = (threadIdx.x < 192) ? g_bsum[threadIdx.x] : 0;
  int lane = threadIdx.x & 31, w = threadIdx.x >> 5;
  int x = v;
  #pragma unroll
  for (int o = 1; o < 32; o <<= 1) { int n = __shfl_up_sync(~0u, x, o); if (lane >= o) x += n; }
  __shared__ int ws[8];
  if (lane == 31) ws[w] = x;
  __syncthreads();
  int prefix = 0;
  for (int i = 0; i < w; i++) prefix += ws[i];
  if (threadIdx.x < 192) g_bsum[threadIdx.x] = prefix + x - v;
}
__global__ void csr_scan3() {                   // 192 blocks x 256
  int gid = blockIdx.x*256 + threadIdx.x;
  int o = g_off[gid] + g_bsum[blockIdx.x];
  g_off[gid] = o;
  g_pos[gid] = o;
  if (gid == 0) g_off[TOTSEG] = TOTEDGE;
}
__global__ void csr_fill(const int* __restrict__ e0, const int* __restrict__ e1,
                         const int* __restrict__ e2, const int* __restrict__ e3) {
  int idx = blockIdx.x*256 + threadIdx.x;
  int r = idx >> 16, e = idx & 0xFFFF;
  const int* ep = (r == 0) ? e0 : (r == 1) ? e1 : (r == 2) ? e2 : e3;
  int dst = ep[NE + e];
  int pos = atomicAdd(&g_pos[rdst_of(r)*NN + dst], 1);
  g_elist[pos] = (r << 16) | e;
}

// ================= fused attention: score + softmax + aggregate + gelu =================
// warp per destination node; grid (NN/8, NT)
__global__ void __launch_bounds__(256) attn_fused(
    const int* __restrict__ e0, const int* __restrict__ e1,
    const int* __restrict__ e2, const int* __restrict__ e3,
    const float* __restrict__ Prel, int l)
{
  __shared__ float ssc[8][MAXDEG][8];
  const int t = blockIdx.y;
  const int wid = threadIdx.x >> 5, lane = threadIdx.x & 31;
  const int node = blockIdx.x*8 + wid;
  const int base = t*NN + node;
  const int off0 = g_off[base];
  const int deg  = g_off[base + 1] - off0;

  const float4* qrow = (const float4*)(g_q + (size_t)t*NXH + (size_t)node*HIDDIM);
  const float4 q0 = qrow[lane], q1 = qrow[lane + 32];
  const float scale = 0.17677669529663687f;
  const int h0 = lane >> 3, h1 = 4 + (lane >> 3);

  float mx = -INFINITY;
  for (int i = 0; i < deg; i++) {
    int p = g_elist[off0 + i];
    int r = p >> 16, e = p & 0xFFFF;
    const int* ep = (r == 0) ? e0 : (r == 1) ? e1 : (r == 2) ? e2 : e3;
    int src = ep[e];
    const float4* kr = (const float4*)(g_krel + (size_t)r*NXH + (size_t)src*HIDDIM);
    float4 k0 = kr[lane], k1 = kr[lane + 32];
    float p0 = q0.x*k0.x + q0.y*k0.y + q0.z*k0.z + q0.w*k0.w;
    float p1 = q1.x*k1.x + q1.y*k1.y + q1.z*k1.z + q1.w*k1.w;
    #pragma unroll
    for (int o = 1; o < 8; o <<= 1) {
      p0 += __shfl_xor_sync(~0u, p0, o);
      p1 += __shfl_xor_sync(~0u, p1, o);
    }
    float slo = __shfl_sync(~0u, p0, (lane & 3)*8);
    float shi = __shfl_sync(~0u, p1, (lane & 3)*8);
    float s = (lane & 4) ? shi : slo;
    if (lane < 8) {
      s *= Prel[(size_t)(l*NRR + r)*NHD + lane] * scale;
      ssc[wid][i][lane] = s;
      mx = fmaxf(mx, s);
    }
  }
  float den = 0.f;
  if (lane < 8) {
    for (int i = 0; i < deg; i++) {
      float ex = expf(ssc[wid][i][lane] - mx);
      ssc[wid][i][lane] = ex;
      den += ex;
    }
  }
  float inv = (lane < 8) ? 1.f/fmaxf(den, 1e-16f) : 0.f;
  float inv0 = __shfl_sync(~0u, inv, h0);
  float inv1 = __shfl_sync(~0u, inv, h1);
  __syncwarp();

  float4 a0 = {0,0,0,0}, a1 = {0,0,0,0};
  for (int i = 0; i < deg; i++) {
    int p = g_elist[off0 + i];
    int r = p >> 16, e = p & 0xFFFF;
    const int* ep = (r == 0) ? e0 : (r == 1) ? e1 : (r == 2) ? e2 : e3;
    int src = ep[e];
    const float4* mr = (const float4*)(g_mrel + (size_t)r*NXH + (size_t)src*HIDDIM);
    float al0 = ssc[wid][i][h0] * inv0;
    float al1 = ssc[wid][i][h1] * inv1;
    float4 m0 = mr[lane], m1 = mr[lane + 32];
    a0.x += al0*m0.x; a0.y += al0*m0.y; a0.z += al0*m0.z; a0.w += al0*m0.w;
    a1.x += al1*m1.x; a1.y += al1*m1.y; a1.z += al1*m1.z; a1.w += al1*m1.w;
  }
  float4* outr = (float4*)(g_agg + (size_t)t*NXH + (size_t)node*HIDDIM);
  float4 o0, o1;
  o0.x = gelu_t(a0.x); o0.y = gelu_t(a0.y); o0.z = gelu_t(a0.z); o0.w = gelu_t(a0.w);
  o1.x = gelu_t(a1.x); o1.y = gelu_t(a1.y); o1.z = gelu_t(a1.z); o1.w = gelu_t(a1.w);
  outr[lane] = o0; outr[lane + 32] = o1;
}

// ================= gated skip + residual + LayerNorm (all 3 types) =================
__global__ void __launch_bounds__(256) skip_ln(
    int l, const float* __restrict__ ln_g, const float* __restrict__ ln_b,
    const float* __restrict__ skipv)
{
  int t = blockIdx.y;
  int wi = l*NT + t;
  const float* g  = ln_g + (size_t)wi*HIDDIM;
  const float* bb = ln_b + (size_t)wi*HIDDIM;
  int row = blockIdx.x, c = threadIdx.x;
  float a = 1.f/(1.f + expf(-skipv[wi]));
  size_t idx = (size_t)t*NXH + (size_t)row*HIDDIM + c;
  float p = g_pre[idx];
  float hh = g_h[idx];
  float y = a*p + (1.f - a)*hh + hh;
  __shared__ float s1[8], s2[8];
  float v1 = y, v2 = y*y;
  #pragma unroll
  for (int o = 16; o; o >>= 1) {
    v1 += __shfl_xor_sync(0xffffffffu, v1, o);
    v2 += __shfl_xor_sync(0xffffffffu, v2, o);
  }
  if ((c & 31) == 0) { s1[c>>5] = v1; s2[c>>5] = v2; }
  __syncthreads();
  float sum = 0.f, sq = 0.f;
  #pragma unroll
  for (int i = 0; i < 8; i++) { sum += s1[i]; sq += s2[i]; }
  float mu = sum*(1.f/256.f);
  float var = sq*(1.f/256.f) - mu*mu;
  float o = (y - mu)*rsqrtf(var + 1e-5f)*g[c] + bb[c];
  g_h[idx] = o;
}

// ================= host orchestration =================
static inline GemmJob JB(const float* Aext, int Aid, long long Aoff,
                         const float* Wext, int Wid, long long Woff,
                         const float* Bext, int Bid, long long Boff,
                         float* Cext, int Cid, long long Coff) {
  GemmJob j; j.Aext=Aext; j.Aid=Aid; j.Aoff=Aoff; j.Wext=Wext; j.Wid=Wid; j.Woff=Woff;
  j.Bext=Bext; j.Bid=Bid; j.Boff=Boff; j.Cext=Cext; j.Cid=Cid; j.Coff=Coff;
  return j;
}

extern "C" void kernel_launch(void* const* d_in, const int* in_sizes, int n_in,
                              void* d_out, int out_size) {
  const float* x[NT]  = {(const float*)d_in[0], (const float*)d_in[1], (const float*)d_in[2]};
  const int* e0 = (const int*)d_in[3];
  const int* e1 = (const int*)d_in[4];
  const int* e2 = (const int*)d_in[5];
  const int* e3 = (const int*)d_in[6];
  const float* Win   = (const float*)d_in[7];
  const float* b_in  = (const float*)d_in[8];
  const float* Kw    = (const float*)d_in[9];
  const float* Kb    = (const float*)d_in[10];
  const float* Qw    = (const float*)d_in[11];
  const float* Qb    = (const float*)d_in[12];
  const float* Vw    = (const float*)d_in[13];
  const float* Vb    = (const float*)d_in[14];
  const float* Arel  = (const float*)d_in[15];
  const float* Mrel  = (const float*)d_in[16];
  const float* Prel  = (const float*)d_in[17];
  const float* Aw    = (const float*)d_in[18];
  const float* Ab    = (const float*)d_in[19];
  const float* skip  = (const float*)d_in[20];
  const float* ln_g  = (const float*)d_in[21];
  const float* ln_b  = (const float*)d_in[22];
  const float* Wout  = (const float*)d_in[23];
  const float* b_out = (const float*)d_in[24];
  float* out = (float*)d_out;

  static const int RSRC[NRR] = {1, 0, 2, 0};

  cudaFuncSetAttribute(gemm_mma, cudaFuncAttributeMaxDynamicSharedMemorySize, GEMM_SMEM);

  // fold relation matrices into K/V weights (per call)
  fold_weights<<<32, 256>>>(Kw, Kb, Vw, Vb, Arel, Mrel);

  // CSR build (per call; reused across layers)
  csr_zero<<<TOTSEG/256, 256>>>();
  csr_count<<<TOTEDGE/256, 256>>>(e0, e1, e2, e3);
  csr_scan1<<<TOTSEG/256, 256>>>();
  csr_scan2<<<1, 256>>>();
  csr_scan3<<<TOTSEG/256, 256>>>();
  csr_fill<<<TOTEDGE/256, 256>>>(e0, e1, e2, e3);

  // input projections
  {
    GemmBatch b = {};
    for (int t = 0; t < NT; t++)
      b.j[t] = JB(x[t], -1, 0, Win + (size_t)t*65536, -1, 0, b_in + t*HIDDIM, -1, 0,
                  nullptr, ID_H, (long long)t*NXH);
    gemm_mma<<<dim3(256, 3), 256, GEMM_SMEM>>>(b);
  }

  for (int l = 0; l < NLL; l++) {
    // Q (3) + Krel (4) + Vrel (4) batched
    {
      GemmBatch b = {};
      int n = 0;
      for (int t = 0; t < NT; t++) {
        long long wi = (long long)(l*NT + t);
        b.j[n++] = JB(nullptr, ID_H, (long long)t*NXH, Qw + wi*65536, -1, 0,
                      Qb + wi*HIDDIM, -1, 0, nullptr, ID_Q, (long long)t*NXH);
      }
      for (int r = 0; r < NRR; r++) {
        long long fo = (long long)(l*NRR + r);
        b.j[n++] = JB(nullptr, ID_H, (long long)RSRC[r]*NXH, nullptr, ID_WF, fo*65536,
                      nullptr, ID_BF, fo*HIDDIM, nullptr, ID_KREL, (long long)r*NXH);
      }
      for (int r = 0; r < NRR; r++) {
        long long fo = (long long)(NLL*NRR + l*NRR + r);
        b.j[n++] = JB(nullptr, ID_H, (long long)RSRC[r]*NXH, nullptr, ID_WF, fo*65536,
                      nullptr, ID_BF, fo*HIDDIM, nullptr, ID_MREL, (long long)r*NXH);
      }
      gemm_mma<<<dim3(256, 11), 256, GEMM_SMEM>>>(b);
    }
    // fused attention (scores + softmax + aggregate + gelu), no atomics
    attn_fused<<<dim3(NN/8, NT), 256>>>(e0, e1, e2, e3, Prel, l);
    // A linear
    {
      GemmBatch b = {};
      for (int t = 0; t < NT; t++) {
        long long wi = (long long)(l*NT + t);
        b.j[t] = JB(nullptr, ID_AGG, (long long)t*NXH, Aw + wi*65536, -1, 0,
                    Ab + wi*HIDDIM, -1, 0, nullptr, ID_PRE, (long long)t*NXH);
      }
      gemm_mma<<<dim3(256, 3), 256, GEMM_SMEM>>>(b);
    }
    // gated skip + residual + LN (all types)
    skip_ln<<<dim3(NN, NT), 256>>>(l, ln_g, ln_b, skip);
  }

  // output projections
  {
    GemmBatch b = {};
    for (int t = 0; t < NT; t++)
      b.j[t] = JB(nullptr, ID_H, (long long)t*NXH, Wout + (size_t)t*65536, -1, 0,
                  b_out + t*HIDDIM, -1, 0, out + (size_t)t*NXH, -1, 0);
    gemm_mma<<<dim3(256, 3), 256, GEMM_SMEM>>>(b);
  }
}

// round 5
// speedup vs baseline: 3.4626x; 1.0987x over previous
#include <cuda_runtime.h>
#include <math.h>
#include <stdint.h>

#define NN 16384
#define HIDDIM 256
#define NHD 8
#define DD 32
#define NE 65536
#define NT 3
#define NRR 4
#define NLL 4
#define NXH (NN*HIDDIM)
#define TOTSEG (NT*NN)
#define TOTEDGE (NRR*NE)
#define MAXDEG 128

// ---------------- device scratch (allocation-free) ----------------
__device__ float g_h[NT*NXH];
__device__ float g_q[NT*NXH];
__device__ float g_krel[NRR*NXH];
__device__ float g_mrel[NRR*NXH];
__device__ float g_agg[NT*NXH];
__device__ float g_wf[2*NLL*NRR*HIDDIM*HIDDIM];
__device__ float g_bf[2*NLL*NRR*HIDDIM];
// CSR
__device__ int g_cnt[TOTSEG];
__device__ int g_off[TOTSEG+1];
__device__ int g_pos[TOTSEG];
__device__ int g_bsum[256];
__device__ int g_elist[TOTEDGE];

#define ID_H 0
#define ID_Q 1
#define ID_KREL 2
#define ID_MREL 3
#define ID_AGG 4
#define ID_WF 5
#define ID_BF 6

__device__ __forceinline__ float* devbuf(int id) {
  switch (id) {
    case ID_H: return g_h; case ID_Q: return g_q; case ID_KREL: return g_krel;
    case ID_MREL: return g_mrel; case ID_AGG: return g_agg;
    case ID_WF: return g_wf; default: return g_bf;
  }
}

__device__ __forceinline__ float gelu_t(float x) {
  float x3 = x*x*x;
  return 0.5f*x*(1.0f + tanhf(0.7978845608028654f*(x + 0.044715f*x3)));
}

__device__ __forceinline__ uint32_t smem_u32(const void* p) {
  uint32_t a;
  asm("{ .reg .u64 t; cvta.to.shared.u64 t, %1; cvt.u32.u64 %0, t; }" : "=r"(a) : "l"(p));
  return a;
}
__device__ __forceinline__ uint32_t f2tf(float f) {
  uint32_t r; asm("cvt.rna.tf32.f32 %0, %1;" : "=r"(r) : "f"(f)); return r;
}

__device__ __forceinline__ void mma_tf32(float* c, const uint32_t* a, const uint32_t* b) {
  asm volatile(
      "mma.sync.aligned.m16n8k8.row.col.f32.tf32.tf32.f32 "
      "{%0,%1,%2,%3}, {%4,%5,%6,%7}, {%8,%9}, {%0,%1,%2,%3};"
      : "+f"(c[0]), "+f"(c[1]), "+f"(c[2]), "+f"(c[3])
      : "r"(a[0]), "r"(a[1]), "r"(a[2]), "r"(a[3]), "r"(b[0]), "r"(b[1]));
}

// ================= generic tf32 GEMM (bias epilogue) =================
struct GemmJob {
  const float* Aext; int Aid; long long Aoff;
  const float* Wext; int Wid; long long Woff;
  const float* Bext; int Bid; long long Boff;
  float* Cext; int Cid; long long Coff;
};
struct GemmBatch { GemmJob j[12]; };

#define APITCH 36
#define BPITCH 136
#define ASZ (128*APITCH)
#define BSZ (32*BPITCH)
#define GEMM_SMEM ((2*ASZ + 2*BSZ)*4)

__global__ void __launch_bounds__(256, 1) gemm_mma(GemmBatch batch) {
  const GemmJob jb = batch.j[blockIdx.y];
  const float* A = jb.Aext ? jb.Aext : (const float*)(devbuf(jb.Aid) + jb.Aoff);
  const float* W = jb.Wext ? jb.Wext : (const float*)(devbuf(jb.Wid) + jb.Woff);
  const float* bias = jb.Bext ? jb.Bext : (const float*)(devbuf(jb.Bid) + jb.Boff);
  float* C = jb.Cext ? jb.Cext : (devbuf(jb.Cid) + jb.Coff);

  const int m0 = (blockIdx.x >> 1) * 128;
  const int n0 = (blockIdx.x & 1) * 128;

  extern __shared__ float sm[];
  float* AsBase = sm;
  float* BsBase = sm + 2*ASZ;
  const uint32_t sA = smem_u32(AsBase);
  const uint32_t sB = smem_u32(BsBase);

  const int tid = threadIdx.x, lane = tid & 31, wid = tid >> 5;
  const int quad = lane >> 2, tc = lane & 3;
  const int wm = (wid & 3) * 32, wn = (wid >> 2) * 64;

  float acc[2][8][4];
  #pragma unroll
  for (int mt = 0; mt < 2; mt++)
    #pragma unroll
    for (int nt = 0; nt < 8; nt++)
      #pragma unroll
      for (int i = 0; i < 4; i++) acc[mt][nt][i] = 0.f;

  auto issue = [&](int buf, int k0) {
    #pragma unroll
    for (int j = 0; j < 4; j++) {
      int t2 = tid + j*256;
      int row = t2 >> 3, seg = t2 & 7;
      const float* src = A + (size_t)(m0 + row)*HIDDIM + k0 + seg*4;
      uint32_t dst = sA + (uint32_t)(buf*ASZ + row*APITCH + seg*4)*4u;
      asm volatile("cp.async.cg.shared.global [%0], [%1], 16;" :: "r"(dst), "l"(src) : "memory");
    }
    #pragma unroll
    for (int j = 0; j < 4; j++) {
      int t2 = tid + j*256;
      int row = t2 >> 5, seg = t2 & 31;
      const float* src = W + (size_t)(k0 + row)*HIDDIM + n0 + seg*4;
      uint32_t dst = sB + (uint32_t)(buf*BSZ + row*BPITCH + seg*4)*4u;
      asm volatile("cp.async.cg.shared.global [%0], [%1], 16;" :: "r"(dst), "l"(src) : "memory");
    }
    asm volatile("cp.async.commit_group;" ::: "memory");
  };

  issue(0, 0);

  for (int ch = 0; ch < 8; ch++) {
    if (ch < 7) issue((ch + 1) & 1, (ch + 1) * 32);
    if (ch < 7) asm volatile("cp.async.wait_group 1;" ::: "memory");
    else        asm volatile("cp.async.wait_group 0;" ::: "memory");
    __syncthreads();

    const float* Ab = AsBase + (ch & 1)*ASZ;
    const float* Bb = BsBase + (ch & 1)*BSZ;
    #pragma unroll
    for (int kk8 = 0; kk8 < 4; kk8++) {
      const int kk = kk8 * 8;
      uint32_t a[2][4], b[8][2];
      #pragma unroll
      for (int mt = 0; mt < 2; mt++) {
        int r = wm + mt*16 + quad;
        a[mt][0] = f2tf(Ab[r*APITCH + kk + tc]);
        a[mt][1] = f2tf(Ab[(r+8)*APITCH + kk + tc]);
        a[mt][2] = f2tf(Ab[r*APITCH + kk + tc + 4]);
        a[mt][3] = f2tf(Ab[(r+8)*APITCH + kk + tc + 4]);
      }
      #pragma unroll
      for (int nt = 0; nt < 8; nt++) {
        int n = wn + nt*8 + quad;
        b[nt][0] = f2tf(Bb[(kk + tc)*BPITCH + n]);
        b[nt][1] = f2tf(Bb[(kk + tc + 4)*BPITCH + n]);
      }
      #pragma unroll
      for (int mt = 0; mt < 2; mt++)
        #pragma unroll
        for (int nt = 0; nt < 8; nt++)
          mma_tf32(acc[mt][nt], a[mt], b[nt]);
    }
    __syncthreads();
  }

  #pragma unroll
  for (int nt = 0; nt < 8; nt++) {
    int cix = n0 + wn + nt*8 + tc*2;
    float2 bv = *(const float2*)(bias + cix);
    #pragma unroll
    for (int mt = 0; mt < 2; mt++) {
      int r = m0 + wm + mt*16 + quad;
      float2 o0; o0.x = acc[mt][nt][0] + bv.x; o0.y = acc[mt][nt][1] + bv.y;
      float2 o1; o1.x = acc[mt][nt][2] + bv.x; o1.y = acc[mt][nt][3] + bv.y;
      *(float2*)(C + (size_t)r*HIDDIM + cix) = o0;
      *(float2*)(C + (size_t)(r+8)*HIDDIM + cix) = o1;
    }
  }
}

// ================= A-linear GEMM fused with gated skip + residual + LayerNorm =================
// 512 threads, CTA tile 128x256 (full rows), writes g_h in place.
#define BPITCH2 264
#define ASZ2 (128*APITCH)
#define BSZ2 (32*BPITCH2)
#define GEMMLN_SMEM ((2*ASZ2 + 2*BSZ2)*4)

__global__ void __launch_bounds__(512, 1) gemm_ln(
    const float* __restrict__ Aw, const float* __restrict__ Ab,
    const float* __restrict__ ln_g, const float* __restrict__ ln_b,
    const float* __restrict__ skipv, int l)
{
  const int t = blockIdx.y;
  const int wi = l*NT + t;
  const float* A = g_agg + (size_t)t*NXH;
  const float* W = Aw + (size_t)wi*65536;
  const float* bias = Ab + (size_t)wi*HIDDIM;
  const float* lg = ln_g + (size_t)wi*HIDDIM;
  const float* lb = ln_b + (size_t)wi*HIDDIM;
  float* H = g_h + (size_t)t*NXH;
  const int m0 = blockIdx.x * 128;

  extern __shared__ float sm[];
  float* AsBase = sm;
  float* BsBase = sm + 2*ASZ2;
  const uint32_t sA = smem_u32(AsBase);
  const uint32_t sB = smem_u32(BsBase);
  __shared__ float ps[128][4], pq[128][4];
  __shared__ float rmu[128], rrs[128];

  const int tid = threadIdx.x, lane = tid & 31, wid = tid >> 5;
  const int quad = lane >> 2, tc = lane & 3;
  const int wm = (wid & 3) * 32, wn = (wid >> 2) * 64;
  const int wnix = wid >> 2;

  float acc[2][8][4];
  #pragma unroll
  for (int mt = 0; mt < 2; mt++)
    #pragma unroll
    for (int nt = 0; nt < 8; nt++)
      #pragma unroll
      for (int i = 0; i < 4; i++) acc[mt][nt][i] = 0.f;

  auto issue = [&](int buf, int k0) {
    #pragma unroll
    for (int j = 0; j < 2; j++) {   // A: 1024 float4
      int t2 = tid + j*512;
      int row = t2 >> 3, seg = t2 & 7;
      const float* src = A + (size_t)(m0 + row)*HIDDIM + k0 + seg*4;
      uint32_t dst = sA + (uint32_t)(buf*ASZ2 + row*APITCH + seg*4)*4u;
      asm volatile("cp.async.cg.shared.global [%0], [%1], 16;" :: "r"(dst), "l"(src) : "memory");
    }
    #pragma unroll
    for (int j = 0; j < 4; j++) {   // B: 32 x 256 = 2048 float4
      int t2 = tid + j*512;
      int row = t2 >> 6, seg = t2 & 63;
      const float* src = W + (size_t)(k0 + row)*HIDDIM + seg*4;
      uint32_t dst = sB + (uint32_t)(buf*BSZ2 + row*BPITCH2 + seg*4)*4u;
      asm volatile("cp.async.cg.shared.global [%0], [%1], 16;" :: "r"(dst), "l"(src) : "memory");
    }
    asm volatile("cp.async.commit_group;" ::: "memory");
  };

  issue(0, 0);

  for (int ch = 0; ch < 8; ch++) {
    if (ch < 7) issue((ch + 1) & 1, (ch + 1) * 32);
    if (ch < 7) asm volatile("cp.async.wait_group 1;" ::: "memory");
    else        asm volatile("cp.async.wait_group 0;" ::: "memory");
    __syncthreads();

    const float* Abf = AsBase + (ch & 1)*ASZ2;
    const float* Bbf = BsBase + (ch & 1)*BSZ2;
    #pragma unroll
    for (int kk8 = 0; kk8 < 4; kk8++) {
      const int kk = kk8 * 8;
      uint32_t a[2][4], b[8][2];
      #pragma unroll
      for (int mt = 0; mt < 2; mt++) {
        int r = wm + mt*16 + quad;
        a[mt][0] = f2tf(Abf[r*APITCH + kk + tc]);
        a[mt][1] = f2tf(Abf[(r+8)*APITCH + kk + tc]);
        a[mt][2] = f2tf(Abf[r*APITCH + kk + tc + 4]);
        a[mt][3] = f2tf(Abf[(r+8)*APITCH + kk + tc + 4]);
      }
      #pragma unroll
      for (int nt = 0; nt < 8; nt++) {
        int n = wn + nt*8 + quad;
        b[nt][0] = f2tf(Bbf[(kk + tc)*BPITCH2 + n]);
        b[nt][1] = f2tf(Bbf[(kk + tc + 4)*BPITCH2 + n]);
      }
      #pragma unroll
      for (int mt = 0; mt < 2; mt++)
        #pragma unroll
        for (int nt = 0; nt < 8; nt++)
          mma_tf32(acc[mt][nt], a[mt], b[nt]);
    }
    __syncthreads();
  }

  // ---- fused epilogue: y = a*(acc+bias) + (1-a)*h + h, then LN(y) -> H ----
  const float ag = 1.f/(1.f + expf(-skipv[wi]));

  // 1) compute y in-place in acc, accumulate per-row partial sums
  #pragma unroll
  for (int mt = 0; mt < 2; mt++) {
    #pragma unroll
    for (int half = 0; half < 2; half++) {
      int rloc = wm + mt*16 + quad + half*8;
      const float* hrow = H + (size_t)(m0 + rloc)*HIDDIM;
      float s = 0.f, q = 0.f;
      #pragma unroll
      for (int nt = 0; nt < 8; nt++) {
        int col = wn + nt*8 + tc*2;
        float2 bv = *(const float2*)(bias + col);
        float2 hv = *(const float2*)(hrow + col);
        float p0 = acc[mt][nt][half*2+0] + bv.x;
        float p1 = acc[mt][nt][half*2+1] + bv.y;
        float y0 = ag*p0 + (1.f - ag)*hv.x + hv.x;
        float y1 = ag*p1 + (1.f - ag)*hv.y + hv.y;
        acc[mt][nt][half*2+0] = y0;
        acc[mt][nt][half*2+1] = y1;
        s += y0 + y1; q += y0*y0 + y1*y1;
      }
      // reduce across tc (4 lanes in same quad-group)
      s += __shfl_xor_sync(~0u, s, 1); q += __shfl_xor_sync(~0u, q, 1);
      s += __shfl_xor_sync(~0u, s, 2); q += __shfl_xor_sync(~0u, q, 2);
      if (tc == 0) { ps[rloc][wnix] = s; pq[rloc][wnix] = q; }
    }
  }
  __syncthreads();
  // 2) per-row stats
  if (tid < 128) {
    float s = ps[tid][0] + ps[tid][1] + ps[tid][2] + ps[tid][3];
    float q = pq[tid][0] + pq[tid][1] + pq[tid][2] + pq[tid][3];
    float mu = s*(1.f/256.f);
    float var = q*(1.f/256.f) - mu*mu;
    rmu[tid] = mu;
    rrs[tid] = rsqrtf(var + 1e-5f);
  }
  __syncthreads();
  // 3) normalize and write
  #pragma unroll
  for (int mt = 0; mt < 2; mt++) {
    #pragma unroll
    for (int half = 0; half < 2; half++) {
      int rloc = wm + mt*16 + quad + half*8;
      float mu = rmu[rloc], rs = rrs[rloc];
      float* hrow = H + (size_t)(m0 + rloc)*HIDDIM;
      #pragma unroll
      for (int nt = 0; nt < 8; nt++) {
        int col = wn + nt*8 + tc*2;
        float2 gv = *(const float2*)(lg + col);
        float2 bv2 = *(const float2*)(lb + col);
        float2 o;
        o.x = (acc[mt][nt][half*2+0] - mu)*rs*gv.x + bv2.x;
        o.y = (acc[mt][nt][half*2+1] - mu)*rs*gv.y + bv2.y;
        *(float2*)(hrow + col) = o;
      }
    }
  }
}

// ================= fold relation matrices into K/V weights =================
__global__ void __launch_bounds__(256) fold_weights(
    const float* __restrict__ Kw, const float* __restrict__ Kb,
    const float* __restrict__ Vw, const float* __restrict__ Vb,
    const float* __restrict__ Arel, const float* __restrict__ Mrel)
{
  int b = blockIdx.x;
  int r = b & 3, l = (b >> 2) & 3, kv = b >> 4;
  const int RSRC[4] = {1, 0, 2, 0};
  int s = RSRC[r];
  const float* W   = (kv ? Vw : Kw) + (size_t)(l*NT + s)*HIDDIM*HIDDIM;
  const float* bb  = (kv ? Vb : Kb) + (size_t)(l*NT + s)*HIDDIM;
  const float* Rel = (kv ? Mrel : Arel) + (size_t)(l*NRR + r)*NHD*DD*DD;
  float* Wo = g_wf + (size_t)(kv*NLL*NRR + l*NRR + r)*HIDDIM*HIDDIM;
  float* bo = g_bf + (size_t)(kv*NLL*NRR + l*NRR + r)*HIDDIM;

  __shared__ float Rs[NHD*DD*DD];
  int tid = threadIdx.x;
  for (int i = tid; i < NHD*DD*DD; i += 256) Rs[i] = Rel[i];
  __syncthreads();

  const float* wrow = W + (size_t)tid*HIDDIM;
  float* worow = Wo + (size_t)tid*HIDDIM;
  for (int h = 0; h < NHD; h++) {
    float xv[DD];
    #pragma unroll
    for (int d = 0; d < DD; d++) xv[d] = wrow[h*DD + d];
    for (int e = 0; e < DD; e++) {
      float acc = 0.f;
      #pragma unroll
      for (int d = 0; d < DD; d++) acc += xv[d] * Rs[(h*DD + d)*DD + e];
      worow[h*DD + e] = acc;
    }
  }
  {
    int h = tid >> 5, e = tid & 31;
    float acc = 0.f;
    #pragma unroll
    for (int d = 0; d < DD; d++) acc += bb[h*DD + d] * Rs[(h*DD + d)*DD + e];
    bo[tid] = acc;
  }
}

// ================= CSR build =================
__device__ __forceinline__ int rdst_of(int r) { return (r == 1) ? 2 : (r == 2) ? 1 : 0; }

__global__ void csr_zero() {
  int i = blockIdx.x*256 + threadIdx.x;
  if (i < TOTSEG) g_cnt[i] = 0;
}
__global__ void csr_count(const int* __restrict__ e0, const int* __restrict__ e1,
                          const int* __restrict__ e2, const int* __restrict__ e3) {
  int idx = blockIdx.x*256 + threadIdx.x;
  int r = idx >> 16, e = idx & 0xFFFF;
  const int* ep = (r == 0) ? e0 : (r == 1) ? e1 : (r == 2) ? e2 : e3;
  int dst = ep[NE + e];
  atomicAdd(&g_cnt[rdst_of(r)*NN + dst], 1);
}
__global__ void csr_scan1() {
  int gid = blockIdx.x*256 + threadIdx.x;
  int v = g_cnt[gid];
  int lane = threadIdx.x & 31, w = threadIdx.x >> 5;
  int x = v;
  #pragma unroll
  for (int o = 1; o < 32; o <<= 1) { int n = __shfl_up_sync(~0u, x, o); if (lane >= o) x += n; }
  __shared__ int ws[8];
  if (lane == 31) ws[w] = x;
  __syncthreads();
  int prefix = 0;
  for (int i = 0; i < w; i++) prefix += ws[i];
  int excl = prefix + x - v;
  g_off[gid] = excl;
  if (threadIdx.x == 255) g_bsum[blockIdx.x] = excl + v;
}
__global__ void csr_scan2() {
  int v = (threadIdx.x < 192) ? g_bsum[threadIdx.x] : 0;
  int lane = threadIdx.x & 31, w = threadIdx.x >> 5;
  int x = v;
  #pragma unroll
  for (int o = 1; o < 32; o <<= 1) { int n = __shfl_up_sync(~0u, x, o); if (lane >= o) x += n; }
  __shared__ int ws[8];
  if (lane == 31) ws[w] = x;
  __syncthreads();
  int prefix = 0;
  for (int i = 0; i < w; i++) prefix += ws[i];
  if (threadIdx.x < 192) g_bsum[threadIdx.x] = prefix + x - v;
}
__global__ void csr_scan3() {
  int gid = blockIdx.x*256 + threadIdx.x;
  int o = g_off[gid] + g_bsum[blockIdx.x];
  g_off[gid] = o;
  g_pos[gid] = o;
  if (gid == 0) g_off[TOTSEG] = TOTEDGE;
}
__global__ void csr_fill(const int* __restrict__ e0, const int* __restrict__ e1,
                         const int* __restrict__ e2, const int* __restrict__ e3) {
  int idx = blockIdx.x*256 + threadIdx.x;
  int r = idx >> 16, e = idx & 0xFFFF;
  const int* ep = (r == 0) ? e0 : (r == 1) ? e1 : (r == 2) ? e2 : e3;
  int dst = ep[NE + e];
  int pos = atomicAdd(&g_pos[rdst_of(r)*NN + dst], 1);
  g_elist[pos] = (r << 16) | e;
}

// ================= fused attention =================
__global__ void __launch_bounds__(256) attn_fused(
    const int* __restrict__ e0, const int* __restrict__ e1,
    const int* __restrict__ e2, const int* __restrict__ e3,
    const float* __restrict__ Prel, int l)
{
  __shared__ float ssc[8][MAXDEG][8];
  const int t = blockIdx.y;
  const int wid = threadIdx.x >> 5, lane = threadIdx.x & 31;
  const int node = blockIdx.x*8 + wid;
  const int base = t*NN + node;
  const int off0 = g_off[base];
  const int deg  = g_off[base + 1] - off0;

  const float4* qrow = (const float4*)(g_q + (size_t)t*NXH + (size_t)node*HIDDIM);
  const float4 q0 = qrow[lane], q1 = qrow[lane + 32];
  const float scale = 0.17677669529663687f;
  const int h0 = lane >> 3, h1 = 4 + (lane >> 3);

  float mx = -INFINITY;
  for (int i = 0; i < deg; i++) {
    int p = g_elist[off0 + i];
    int r = p >> 16, e = p & 0xFFFF;
    const int* ep = (r == 0) ? e0 : (r == 1) ? e1 : (r == 2) ? e2 : e3;
    int src = ep[e];
    const float4* kr = (const float4*)(g_krel + (size_t)r*NXH + (size_t)src*HIDDIM);
    float4 k0 = kr[lane], k1 = kr[lane + 32];
    float p0 = q0.x*k0.x + q0.y*k0.y + q0.z*k0.z + q0.w*k0.w;
    float p1 = q1.x*k1.x + q1.y*k1.y + q1.z*k1.z + q1.w*k1.w;
    #pragma unroll
    for (int o = 1; o < 8; o <<= 1) {
      p0 += __shfl_xor_sync(~0u, p0, o);
      p1 += __shfl_xor_sync(~0u, p1, o);
    }
    float slo = __shfl_sync(~0u, p0, (lane & 3)*8);
    float shi = __shfl_sync(~0u, p1, (lane & 3)*8);
    float s = (lane & 4) ? shi : slo;
    if (lane < 8) {
      s *= Prel[(size_t)(l*NRR + r)*NHD + lane] * scale;
      ssc[wid][i][lane] = s;
      mx = fmaxf(mx, s);
    }
  }
  float den = 0.f;
  if (lane < 8) {
    for (int i = 0; i < deg; i++) {
      float ex = expf(ssc[wid][i][lane] - mx);
      ssc[wid][i][lane] = ex;
      den += ex;
    }
  }
  float inv = (lane < 8) ? 1.f/fmaxf(den, 1e-16f) : 0.f;
  float inv0 = __shfl_sync(~0u, inv, h0);
  float inv1 = __shfl_sync(~0u, inv, h1);
  __syncwarp();

  float4 a0 = {0,0,0,0}, a1 = {0,0,0,0};
  for (int i = 0; i < deg; i++) {
    int p = g_elist[off0 + i];
    int r = p >> 16, e = p & 0xFFFF;
    const int* ep = (r == 0) ? e0 : (r == 1) ? e1 : (r == 2) ? e2 : e3;
    int src = ep[e];
    const float4* mr = (const float4*)(g_mrel + (size_t)r*NXH + (size_t)src*HIDDIM);
    float al0 = ssc[wid][i][h0] * inv0;
    float al1 = ssc[wid][i][h1] * inv1;
    float4 m0 = mr[lane], m1 = mr[lane + 32];
    a0.x += al0*m0.x; a0.y += al0*m0.y; a0.z += al0*m0.z; a0.w += al0*m0.w;
    a1.x += al1*m1.x; a1.y += al1*m1.y; a1.z += al1*m1.z; a1.w += al1*m1.w;
  }
  float4* outr = (float4*)(g_agg + (size_t)t*NXH + (size_t)node*HIDDIM);
  float4 o0, o1;
  o0.x = gelu_t(a0.x); o0.y = gelu_t(a0.y); o0.z = gelu_t(a0.z); o0.w = gelu_t(a0.w);
  o1.x = gelu_t(a1.x); o1.y = gelu_t(a1.y); o1.z = gelu_t(a1.z); o1.w = gelu_t(a1.w);
  outr[lane] = o0; outr[lane + 32] = o1;
}

// ================= host orchestration =================
static inline GemmJob JB(const float* Aext, int Aid, long long Aoff,
                         const float* Wext, int Wid, long long Woff,
                         const float* Bext, int Bid, long long Boff,
                         float* Cext, int Cid, long long Coff) {
  GemmJob j; j.Aext=Aext; j.Aid=Aid; j.Aoff=Aoff; j.Wext=Wext; j.Wid=Wid; j.Woff=Woff;
  j.Bext=Bext; j.Bid=Bid; j.Boff=Boff; j.Cext=Cext; j.Cid=Cid; j.Coff=Coff;
  return j;
}

extern "C" void kernel_launch(void* const* d_in, const int* in_sizes, int n_in,
                              void* d_out, int out_size) {
  const float* x[NT]  = {(const float*)d_in[0], (const float*)d_in[1], (const float*)d_in[2]};
  const int* e0 = (const int*)d_in[3];
  const int* e1 = (const int*)d_in[4];
  const int* e2 = (const int*)d_in[5];
  const int* e3 = (const int*)d_in[6];
  const float* Win   = (const float*)d_in[7];
  const float* b_in  = (const float*)d_in[8];
  const float* Kw    = (const float*)d_in[9];
  const float* Kb    = (const float*)d_in[10];
  const float* Qw    = (const float*)d_in[11];
  const float* Qb    = (const float*)d_in[12];
  const float* Vw    = (const float*)d_in[13];
  const float* Vb    = (const float*)d_in[14];
  const float* Arel  = (const float*)d_in[15];
  const float* Mrel  = (const float*)d_in[16];
  const float* Prel  = (const float*)d_in[17];
  const float* Aw    = (const float*)d_in[18];
  const float* Ab    = (const float*)d_in[19];
  const float* skip  = (const float*)d_in[20];
  const float* ln_g  = (const float*)d_in[21];
  const float* ln_b  = (const float*)d_in[22];
  const float* Wout  = (const float*)d_in[23];
  const float* b_out = (const float*)d_in[24];
  float* out = (float*)d_out;

  static const int RSRC[NRR] = {1, 0, 2, 0};

  cudaFuncSetAttribute(gemm_mma, cudaFuncAttributeMaxDynamicSharedMemorySize, GEMM_SMEM);
  cudaFuncSetAttribute(gemm_ln, cudaFuncAttributeMaxDynamicSharedMemorySize, GEMMLN_SMEM);

  fold_weights<<<32, 256>>>(Kw, Kb, Vw, Vb, Arel, Mrel);

  csr_zero<<<TOTSEG/256, 256>>>();
  csr_count<<<TOTEDGE/256, 256>>>(e0, e1, e2, e3);
  csr_scan1<<<TOTSEG/256, 256>>>();
  csr_scan2<<<1, 256>>>();
  csr_scan3<<<TOTSEG/256, 256>>>();
  csr_fill<<<TOTEDGE/256, 256>>>(e0, e1, e2, e3);

  // input projections
  {
    GemmBatch b = {};
    for (int t = 0; t < NT; t++)
      b.j[t] = JB(x[t], -1, 0, Win + (size_t)t*65536, -1, 0, b_in + t*HIDDIM, -1, 0,
                  nullptr, ID_H, (long long)t*NXH);
    gemm_mma<<<dim3(256, 3), 256, GEMM_SMEM>>>(b);
  }

  for (int l = 0; l < NLL; l++) {
    // Q (3) + Krel (4) + Vrel (4) batched
    {
      GemmBatch b = {};
      int n = 0;
      for (int t = 0; t < NT; t++) {
        long long wi = (long long)(l*NT + t);
        b.j[n++] = JB(nullptr, ID_H, (long long)t*NXH, Qw + wi*65536, -1, 0,
                      Qb + wi*HIDDIM, -1, 0, nullptr, ID_Q, (long long)t*NXH);
      }
      for (int r = 0; r < NRR; r++) {
        long long fo = (long long)(l*NRR + r);
        b.j[n++] = JB(nullptr, ID_H, (long long)RSRC[r]*NXH, nullptr, ID_WF, fo*65536,
                      nullptr, ID_BF, fo*HIDDIM, nullptr, ID_KREL, (long long)r*NXH);
      }
      for (int r = 0; r < NRR; r++) {
        long long fo = (long long)(NLL*NRR + l*NRR + r);
        b.j[n++] = JB(nullptr, ID_H, (long long)RSRC[r]*NXH, nullptr, ID_WF, fo*65536,
                      nullptr, ID_BF, fo*HIDDIM, nullptr, ID_MREL, (long long)r*NXH);
      }
      gemm_mma<<<dim3(256, 11), 256, GEMM_SMEM>>>(b);
    }
    // fused attention (scores + softmax + aggregate + gelu)
    attn_fused<<<dim3(NN/8, NT), 256>>>(e0, e1, e2, e3, Prel, l);
    // A-linear fused with gated skip + residual + LayerNorm
    gemm_ln<<<dim3(128, 3), 512, GEMMLN_SMEM>>>(Aw, Ab, ln_g, ln_b, skip, l);
  }

  // output projections
  {
    GemmBatch b = {};
    for (int t = 0; t < NT; t++)
      b.j[t] = JB(nullptr, ID_H, (long long)t*NXH, Wout + (size_t)t*65536, -1, 0,
                  b_out + t*HIDDIM, -1, 0, out + (size_t)t*NXH, -1, 0);
    gemm_mma<<<dim3(256, 3), 256, GEMM_SMEM>>>(b);
  }
}

// round 6
// speedup vs baseline: 4.0731x; 1.1763x over previous
#include <cuda_runtime.h>
#include <cuda_fp16.h>
#include <math.h>
#include <stdint.h>

#define NN 16384
#define HIDDIM 256
#define NHD 8
#define DD 32
#define NE 65536
#define NT 3
#define NRR 4
#define NLL 4
#define NXH (NN*HIDDIM)
#define TOTSEG (NT*NN)
#define TOTEDGE (NRR*NE)
#define MAXDEG 128
#define NMATS 62

// ---------------- device scratch (allocation-free) ----------------
__device__ float g_h[NT*NXH];
__device__ float g_q[NT*NXH];
__device__ float g_krel[NRR*NXH];
__device__ float g_mrel[NRR*NXH];
__device__ float g_agg[NT*NXH];
__device__ float g_wf[2*NLL*NRR*HIDDIM*HIDDIM];
__device__ float g_bf[2*NLL*NRR*HIDDIM];
__device__ __half g_wh[NMATS*HIDDIM*HIDDIM];   // all weights, fp16, transposed [n][k]
// CSR
__device__ int g_cnt[TOTSEG];
__device__ int g_off[TOTSEG+1];
__device__ int g_pos[TOTSEG];
__device__ int g_bsum[256];
__device__ int g_elist[TOTEDGE];

#define ID_H 0
#define ID_Q 1
#define ID_KREL 2
#define ID_MREL 3
#define ID_AGG 4
#define ID_BF 5

__device__ __forceinline__ float* devbuf(int id) {
  switch (id) {
    case ID_H: return g_h; case ID_Q: return g_q; case ID_KREL: return g_krel;
    case ID_MREL: return g_mrel; case ID_AGG: return g_agg; default: return g_bf;
  }
}

__device__ __forceinline__ float gelu_t(float x) {
  float x3 = x*x*x;
  return 0.5f*x*(1.0f + tanhf(0.7978845608028654f*(x + 0.044715f*x3)));
}

__device__ __forceinline__ uint32_t smem_u32(const void* p) {
  uint32_t a;
  asm("{ .reg .u64 t; cvta.to.shared.u64 t, %1; cvt.u32.u64 %0, t; }" : "=r"(a) : "l"(p));
  return a;
}

__device__ __forceinline__ void mma_f16(float* c, const uint32_t* a, const uint32_t* b) {
  asm volatile(
      "mma.sync.aligned.m16n8k16.row.col.f32.f16.f16.f32 "
      "{%0,%1,%2,%3}, {%4,%5,%6,%7}, {%8,%9}, {%0,%1,%2,%3};"
      : "+f"(c[0]), "+f"(c[1]), "+f"(c[2]), "+f"(c[3])
      : "r"(a[0]), "r"(a[1]), "r"(a[2]), "r"(a[3]), "r"(b[0]), "r"(b[1]));
}

// ================= weight convert+transpose: f32 [k][n] -> fp16 [n][k] =================
// matrix index map: 0..2 Win[t], 3..14 Qw[l*3+t], 15..30 wfK[l*4+r], 31..46 wfV[l*4+r],
//                   47..58 Aw[l*3+t], 59..61 Wout[t]
__global__ void __launch_bounds__(256) conv_weights(
    const float* __restrict__ Win, const float* __restrict__ Qw,
    const float* __restrict__ Aw,  const float* __restrict__ Wout)
{
  int m = blockIdx.y;
  const float* W;
  if (m < 3)        W = Win  + (size_t)m*65536;
  else if (m < 15)  W = Qw   + (size_t)(m-3)*65536;
  else if (m < 47)  W = g_wf + (size_t)(m-15)*65536;
  else if (m < 59)  W = Aw   + (size_t)(m-47)*65536;
  else              W = Wout + (size_t)(m-59)*65536;
  __half* Wt = g_wh + (size_t)m*65536;

  int tn = (blockIdx.x & 7) * 32;     // n tile
  int tk = (blockIdx.x >> 3) * 32;    // k tile
  __shared__ __half tile[32][33];
  int tid = threadIdx.x;
  #pragma unroll
  for (int j = 0; j < 4; j++) {
    int idx = tid + j*256;
    int kk = idx >> 5, nn = idx & 31;
    tile[kk][nn] = __float2half_rn(W[(size_t)(tk + kk)*HIDDIM + tn + nn]);
  }
  __syncthreads();
  #pragma unroll
  for (int j = 0; j < 4; j++) {
    int idx = tid + j*256;
    int nn = idx >> 5, kk = idx & 31;
    Wt[(size_t)(tn + nn)*HIDDIM + tk + kk] = tile[kk][nn];
  }
}

// ================= unified fp16 GEMM: C[16384,256] = A @ W + bias  (+ optional skip/LN) =================
// 512 threads, CTA tile 128x256 (full rows), 16 warps of 32x64, K chunks of 32.
struct GemmJob {
  const float* Aext; int Aid; long long Aoff;
  int widx;                               // index into g_wh
  const float* Bext; int Bid; long long Boff;
  float* Cext; int Cid; long long Coff;   // mode 0 output
  int mode;                               // 0: bias->C   1: bias+skip+residual+LN->g_h
  int wi; int t;                          // mode 1 params
};
struct GemmBatch { GemmJob j[12]; };

#define AP 40                     // halves per A smem row (32+8)
#define BP 40                     // halves per B smem row
#define ASZH (128*AP)             // 5120 halves
#define BSZH (256*BP)             // 10240 halves
#define GEMM_SMEM ((2*ASZH + 2*BSZH)*2)   // 61440 bytes

__global__ void __launch_bounds__(512, 1) gemm_h(GemmBatch batch,
    const float* __restrict__ ln_g, const float* __restrict__ ln_b,
    const float* __restrict__ skipv)
{
  const GemmJob jb = batch.j[blockIdx.y];
  const float* A = jb.Aext ? jb.Aext : (const float*)(devbuf(jb.Aid) + jb.Aoff);
  const __half* Wt = g_wh + (size_t)jb.widx*65536;
  const float* bias = jb.Bext ? jb.Bext : (const float*)(devbuf(jb.Bid) + jb.Boff);
  const int m0 = blockIdx.x * 128;

  extern __shared__ __half smh[];
  __half* As = smh;                 // 2 x ASZH
  __half* Bs = smh + 2*ASZH;        // 2 x BSZH
  const uint32_t sB = smem_u32(Bs);
  __shared__ float ps[128][4], pq[128][4];
  __shared__ float rmu[128], rrs[128];

  const int tid = threadIdx.x, lane = tid & 31, wid = tid >> 5;
  const int quad = lane >> 2, tc = lane & 3;
  const int wm = (wid & 3) * 32, wn = (wid >> 2) * 64;
  const int wnix = wid >> 2;

  float acc[2][8][4];
  #pragma unroll
  for (int mt = 0; mt < 2; mt++)
    #pragma unroll
    for (int nt = 0; nt < 8; nt++)
      #pragma unroll
      for (int i = 0; i < 4; i++) acc[mt][nt][i] = 0.f;

  // A chunk register staging (2 float4 per thread)
  const int arow = tid >> 3, aseg = tid & 7;           // handles rows 0..63 (+64 on 2nd)
  float4 areg0, areg1;
  auto ldA = [&](int k0) {
    areg0 = *(const float4*)(A + (size_t)(m0 + arow)*HIDDIM + k0 + aseg*4);
    areg1 = *(const float4*)(A + (size_t)(m0 + arow + 64)*HIDDIM + k0 + aseg*4);
  };
  auto stA = [&](int buf) {
    __half2 h01 = __floats2half2_rn(areg0.x, areg0.y);
    __half2 h23 = __floats2half2_rn(areg0.z, areg0.w);
    uint2 pk; pk.x = *(uint32_t*)&h01; pk.y = *(uint32_t*)&h23;
    *(uint2*)(As + buf*ASZH + arow*AP + aseg*4) = pk;
    h01 = __floats2half2_rn(areg1.x, areg1.y);
    h23 = __floats2half2_rn(areg1.z, areg1.w);
    pk.x = *(uint32_t*)&h01; pk.y = *(uint32_t*)&h23;
    *(uint2*)(As + buf*ASZH + (arow + 64)*AP + aseg*4) = pk;
  };
  auto issueB = [&](int buf, int k0) {
    #pragma unroll
    for (int j = 0; j < 2; j++) {
      int idx = tid + j*512;
      int n = idx >> 2, seg = idx & 3;
      const __half* src = Wt + (size_t)n*HIDDIM + k0 + seg*8;
      uint32_t dst = sB + (uint32_t)(buf*BSZH + n*BP + seg*8)*2u;
      asm volatile("cp.async.cg.shared.global [%0], [%1], 16;" :: "r"(dst), "l"(src) : "memory");
    }
    asm volatile("cp.async.commit_group;" ::: "memory");
  };

  ldA(0);
  issueB(0, 0);

  for (int ch = 0; ch < 8; ch++) {
    int buf = ch & 1;
    stA(buf);
    if (ch < 7) { ldA((ch + 1)*32); issueB((ch + 1) & 1, (ch + 1)*32); }
    if (ch < 7) asm volatile("cp.async.wait_group 1;" ::: "memory");
    else        asm volatile("cp.async.wait_group 0;" ::: "memory");
    __syncthreads();

    const uint32_t* A32 = (const uint32_t*)(As + buf*ASZH);
    const uint32_t* B32 = (const uint32_t*)(Bs + buf*BSZH);
    #pragma unroll
    for (int s = 0; s < 2; s++) {
      const int kh = s*8;   // k offset in uint32 units (16 halves)
      uint32_t a[2][4], b[8][2];
      #pragma unroll
      for (int mt = 0; mt < 2; mt++) {
        int r = wm + mt*16 + quad;
        a[mt][0] = A32[r*(AP/2) + kh + tc];
        a[mt][1] = A32[(r+8)*(AP/2) + kh + tc];
        a[mt][2] = A32[r*(AP/2) + kh + 4 + tc];
        a[mt][3] = A32[(r+8)*(AP/2) + kh + 4 + tc];
      }
      #pragma unroll
      for (int nt = 0; nt < 8; nt++) {
        int n = wn + nt*8 + quad;
        b[nt][0] = B32[n*(BP/2) + kh + tc];
        b[nt][1] = B32[n*(BP/2) + kh + 4 + tc];
      }
      #pragma unroll
      for (int mt = 0; mt < 2; mt++)
        #pragma unroll
        for (int nt = 0; nt < 8; nt++)
          mma_f16(acc[mt][nt], a[mt], b[nt]);
    }
    __syncthreads();
  }

  if (jb.mode == 0) {
    float* C = jb.Cext ? jb.Cext : (devbuf(jb.Cid) + jb.Coff);
    #pragma unroll
    for (int nt = 0; nt < 8; nt++) {
      int cix = wn + nt*8 + tc*2;
      float2 bv = *(const float2*)(bias + cix);
      #pragma unroll
      for (int mt = 0; mt < 2; mt++) {
        int r = m0 + wm + mt*16 + quad;
        float2 o0; o0.x = acc[mt][nt][0] + bv.x; o0.y = acc[mt][nt][1] + bv.y;
        float2 o1; o1.x = acc[mt][nt][2] + bv.x; o1.y = acc[mt][nt][3] + bv.y;
        *(float2*)(C + (size_t)r*HIDDIM + cix) = o0;
        *(float2*)(C + (size_t)(r+8)*HIDDIM + cix) = o1;
      }
    }
  } else {
    // fused gated skip + residual + LayerNorm, in-place on g_h[t]
    const int wi = jb.wi;
    const float* lg = ln_g + (size_t)wi*HIDDIM;
    const float* lb = ln_b + (size_t)wi*HIDDIM;
    float* H = g_h + (size_t)jb.t*NXH;
    const float ag = 1.f/(1.f + expf(-skipv[wi]));

    #pragma unroll
    for (int mt = 0; mt < 2; mt++) {
      #pragma unroll
      for (int half = 0; half < 2; half++) {
        int rloc = wm + mt*16 + quad + half*8;
        const float* hrow = H + (size_t)(m0 + rloc)*HIDDIM;
        float s = 0.f, q = 0.f;
        #pragma unroll
        for (int nt = 0; nt < 8; nt++) {
          int col = wn + nt*8 + tc*2;
          float2 bv = *(const float2*)(bias + col);
          float2 hv = *(const float2*)(hrow + col);
          float p0 = acc[mt][nt][half*2+0] + bv.x;
          float p1 = acc[mt][nt][half*2+1] + bv.y;
          float y0 = ag*p0 + (1.f - ag)*hv.x + hv.x;
          float y1 = ag*p1 + (1.f - ag)*hv.y + hv.y;
          acc[mt][nt][half*2+0] = y0;
          acc[mt][nt][half*2+1] = y1;
          s += y0 + y1; q += y0*y0 + y1*y1;
        }
        s += __shfl_xor_sync(~0u, s, 1); q += __shfl_xor_sync(~0u, q, 1);
        s += __shfl_xor_sync(~0u, s, 2); q += __shfl_xor_sync(~0u, q, 2);
        if (tc == 0) { ps[rloc][wnix] = s; pq[rloc][wnix] = q; }
      }
    }
    __syncthreads();
    if (tid < 128) {
      float s = ps[tid][0] + ps[tid][1] + ps[tid][2] + ps[tid][3];
      float q = pq[tid][0] + pq[tid][1] + pq[tid][2] + pq[tid][3];
      float mu = s*(1.f/256.f);
      float var = q*(1.f/256.f) - mu*mu;
      rmu[tid] = mu;
      rrs[tid] = rsqrtf(var + 1e-5f);
    }
    __syncthreads();
    #pragma unroll
    for (int mt = 0; mt < 2; mt++) {
      #pragma unroll
      for (int half = 0; half < 2; half++) {
        int rloc = wm + mt*16 + quad + half*8;
        float mu = rmu[rloc], rs = rrs[rloc];
        float* hrow = H + (size_t)(m0 + rloc)*HIDDIM;
        #pragma unroll
        for (int nt = 0; nt < 8; nt++) {
          int col = wn + nt*8 + tc*2;
          float2 gv = *(const float2*)(lg + col);
          float2 bv2 = *(const float2*)(lb + col);
          float2 o;
          o.x = (acc[mt][nt][half*2+0] - mu)*rs*gv.x + bv2.x;
          o.y = (acc[mt][nt][half*2+1] - mu)*rs*gv.y + bv2.y;
          *(float2*)(hrow + col) = o;
        }
      }
    }
  }
}

// ================= fold relation matrices into K/V weights =================
__global__ void __launch_bounds__(256) fold_weights(
    const float* __restrict__ Kw, const float* __restrict__ Kb,
    const float* __restrict__ Vw, const float* __restrict__ Vb,
    const float* __restrict__ Arel, const float* __restrict__ Mrel)
{
  int b = blockIdx.x;
  int r = b & 3, l = (b >> 2) & 3, kv = b >> 4;
  const int RSRC[4] = {1, 0, 2, 0};
  int s = RSRC[r];
  const float* W   = (kv ? Vw : Kw) + (size_t)(l*NT + s)*HIDDIM*HIDDIM;
  const float* bb  = (kv ? Vb : Kb) + (size_t)(l*NT + s)*HIDDIM;
  const float* Rel = (kv ? Mrel : Arel) + (size_t)(l*NRR + r)*NHD*DD*DD;
  float* Wo = g_wf + (size_t)(kv*NLL*NRR + l*NRR + r)*HIDDIM*HIDDIM;
  float* bo = g_bf + (size_t)(kv*NLL*NRR + l*NRR + r)*HIDDIM;

  __shared__ float Rs[NHD*DD*DD];
  int tid = threadIdx.x;
  for (int i = tid; i < NHD*DD*DD; i += 256) Rs[i] = Rel[i];
  __syncthreads();

  const float* wrow = W + (size_t)tid*HIDDIM;
  float* worow = Wo + (size_t)tid*HIDDIM;
  for (int h = 0; h < NHD; h++) {
    float xv[DD];
    #pragma unroll
    for (int d = 0; d < DD; d++) xv[d] = wrow[h*DD + d];
    for (int e = 0; e < DD; e++) {
      float acc = 0.f;
      #pragma unroll
      for (int d = 0; d < DD; d++) acc += xv[d] * Rs[(h*DD + d)*DD + e];
      worow[h*DD + e] = acc;
    }
  }
  {
    int h = tid >> 5, e = tid & 31;
    float acc = 0.f;
    #pragma unroll
    for (int d = 0; d < DD; d++) acc += bb[h*DD + d] * Rs[(h*DD + d)*DD + e];
    bo[tid] = acc;
  }
}

// ================= CSR build =================
__device__ __forceinline__ int rdst_of(int r) { return (r == 1) ? 2 : (r == 2) ? 1 : 0; }

__global__ void csr_zero() {
  int i = blockIdx.x*256 + threadIdx.x;
  if (i < TOTSEG) g_cnt[i] = 0;
}
__global__ void csr_count(const int* __restrict__ e0, const int* __restrict__ e1,
                          const int* __restrict__ e2, const int* __restrict__ e3) {
  int idx = blockIdx.x*256 + threadIdx.x;
  int r = idx >> 16, e = idx & 0xFFFF;
  const int* ep = (r == 0) ? e0 : (r == 1) ? e1 : (r == 2) ? e2 : e3;
  int dst = ep[NE + e];
  atomicAdd(&g_cnt[rdst_of(r)*NN + dst], 1);
}
__global__ void csr_scan1() {
  int gid = blockIdx.x*256 + threadIdx.x;
  int v = g_cnt[gid];
  int lane = threadIdx.x & 31, w = threadIdx.x >> 5;
  int x = v;
  #pragma unroll
  for (int o = 1; o < 32; o <<= 1) { int n = __shfl_up_sync(~0u, x, o); if (lane >= o) x += n; }
  __shared__ int ws[8];
  if (lane == 31) ws[w] = x;
  __syncthreads();
  int prefix = 0;
  for (int i = 0; i < w; i++) prefix += ws[i];
  int excl = prefix + x - v;
  g_off[gid] = excl;
  if (threadIdx.x == 255) g_bsum[blockIdx.x] = excl + v;
}
__global__ void csr_scan2() {
  int v = (threadIdx.x < 192) ? g_bsum[threadIdx.x] : 0;
  int lane = threadIdx.x & 31, w = threadIdx.x >> 5;
  int x = v;
  #pragma unroll
  for (int o = 1; o < 32; o <<= 1) { int n = __shfl_up_sync(~0u, x, o); if (lane >= o) x += n; }
  __shared__ int ws[8];
  if (lane == 31) ws[w] = x;
  __syncthreads();
  int prefix = 0;
  for (int i = 0; i < w; i++) prefix += ws[i];
  if (threadIdx.x < 192) g_bsum[threadIdx.x] = prefix + x - v;
}
__global__ void csr_scan3() {
  int gid = blockIdx.x*256 + threadIdx.x;
  int o = g_off[gid] + g_bsum[blockIdx.x];
  g_off[gid] = o;
  g_pos[gid] = o;
  if (gid == 0) g_off[TOTSEG] = TOTEDGE;
}
__global__ void csr_fill(const int* __restrict__ e0, const int* __restrict__ e1,
                         const int* __restrict__ e2, const int* __restrict__ e3) {
  int idx = blockIdx.x*256 + threadIdx.x;
  int r = idx >> 16, e = idx & 0xFFFF;
  const int* ep = (r == 0) ? e0 : (r == 1) ? e1 : (r == 2) ? e2 : e3;
  int dst = ep[NE + e];
  int pos = atomicAdd(&g_pos[rdst_of(r)*NN + dst], 1);
  g_elist[pos] = (r << 16) | e;
}

// ================= fused attention =================
__global__ void __launch_bounds__(256) attn_fused(
    const int* __restrict__ e0, const int* __restrict__ e1,
    const int* __restrict__ e2, const int* __restrict__ e3,
    const float* __restrict__ Prel, int l)
{
  __shared__ float ssc[8][MAXDEG][8];
  const int t = blockIdx.y;
  const int wid = threadIdx.x >> 5, lane = threadIdx.x & 31;
  const int node = blockIdx.x*8 + wid;
  const int base = t*NN + node;
  const int off0 = g_off[base];
  const int deg  = g_off[base + 1] - off0;

  const float4* qrow = (const float4*)(g_q + (size_t)t*NXH + (size_t)node*HIDDIM);
  const float4 q0 = qrow[lane], q1 = qrow[lane + 32];
  const float scale = 0.17677669529663687f;
  const int h0 = lane >> 3, h1 = 4 + (lane >> 3);

  float mx = -INFINITY;
  for (int i = 0; i < deg; i++) {
    int p = g_elist[off0 + i];
    int r = p >> 16, e = p & 0xFFFF;
    const int* ep = (r == 0) ? e0 : (r == 1) ? e1 : (r == 2) ? e2 : e3;
    int src = ep[e];
    const float4* kr = (const float4*)(g_krel + (size_t)r*NXH + (size_t)src*HIDDIM);
    float4 k0 = kr[lane], k1 = kr[lane + 32];
    float p0 = q0.x*k0.x + q0.y*k0.y + q0.z*k0.z + q0.w*k0.w;
    float p1 = q1.x*k1.x + q1.y*k1.y + q1.z*k1.z + q1.w*k1.w;
    #pragma unroll
    for (int o = 1; o < 8; o <<= 1) {
      p0 += __shfl_xor_sync(~0u, p0, o);
      p1 += __shfl_xor_sync(~0u, p1, o);
    }
    float slo = __shfl_sync(~0u, p0, (lane & 3)*8);
    float shi = __shfl_sync(~0u, p1, (lane & 3)*8);
    float s = (lane & 4) ? shi : slo;
    if (lane < 8) {
      s *= Prel[(size_t)(l*NRR + r)*NHD + lane] * scale;
      ssc[wid][i][lane] = s;
      mx = fmaxf(mx, s);
    }
  }
  float den = 0.f;
  if (lane < 8) {
    for (int i = 0; i < deg; i++) {
      float ex = expf(ssc[wid][i][lane] - mx);
      ssc[wid][i][lane] = ex;
      den += ex;
    }
  }
  float inv = (lane < 8) ? 1.f/fmaxf(den, 1e-16f) : 0.f;
  float inv0 = __shfl_sync(~0u, inv, h0);
  float inv1 = __shfl_sync(~0u, inv, h1);
  __syncwarp();

  float4 a0 = {0,0,0,0}, a1 = {0,0,0,0};
  for (int i = 0; i < deg; i++) {
    int p = g_elist[off0 + i];
    int r = p >> 16, e = p & 0xFFFF;
    const int* ep = (r == 0) ? e0 : (r == 1) ? e1 : (r == 2) ? e2 : e3;
    int src = ep[e];
    const float4* mr = (const float4*)(g_mrel + (size_t)r*NXH + (size_t)src*HIDDIM);
    float al0 = ssc[wid][i][h0] * inv0;
    float al1 = ssc[wid][i][h1] * inv1;
    float4 m0 = mr[lane], m1 = mr[lane + 32];
    a0.x += al0*m0.x; a0.y += al0*m0.y; a0.z += al0*m0.z; a0.w += al0*m0.w;
    a1.x += al1*m1.x; a1.y += al1*m1.y; a1.z += al1*m1.z; a1.w += al1*m1.w;
  }
  float4* outr = (float4*)(g_agg + (size_t)t*NXH + (size_t)node*HIDDIM);
  float4 o0, o1;
  o0.x = gelu_t(a0.x); o0.y = gelu_t(a0.y); o0.z = gelu_t(a0.z); o0.w = gelu_t(a0.w);
  o1.x = gelu_t(a1.x); o1.y = gelu_t(a1.y); o1.z = gelu_t(a1.z); o1.w = gelu_t(a1.w);
  outr[lane] = o0; outr[lane + 32] = o1;
}

// ================= host orchestration =================
static inline GemmJob JB(const float* Aext, int Aid, long long Aoff, int widx,
                         const float* Bext, int Bid, long long Boff,
                         float* Cext, int Cid, long long Coff,
                         int mode, int wi, int t) {
  GemmJob j; j.Aext=Aext; j.Aid=Aid; j.Aoff=Aoff; j.widx=widx;
  j.Bext=Bext; j.Bid=Bid; j.Boff=Boff; j.Cext=Cext; j.Cid=Cid; j.Coff=Coff;
  j.mode=mode; j.wi=wi; j.t=t;
  return j;
}

extern "C" void kernel_launch(void* const* d_in, const int* in_sizes, int n_in,
                              void* d_out, int out_size) {
  const float* x[NT]  = {(const float*)d_in[0], (const float*)d_in[1], (const float*)d_in[2]};
  const int* e0 = (const int*)d_in[3];
  const int* e1 = (const int*)d_in[4];
  const int* e2 = (const int*)d_in[5];
  const int* e3 = (const int*)d_in[6];
  const float* Win   = (const float*)d_in[7];
  const float* b_in  = (const float*)d_in[8];
  const float* Kw    = (const float*)d_in[9];
  const float* Kb    = (const float*)d_in[10];
  const float* Qw    = (const float*)d_in[11];
  const float* Qb    = (const float*)d_in[12];
  const float* Vw    = (const float*)d_in[13];
  const float* Vb    = (const float*)d_in[14];
  const float* Arel  = (const float*)d_in[15];
  const float* Mrel  = (const float*)d_in[16];
  const float* Prel  = (const float*)d_in[17];
  const float* Aw    = (const float*)d_in[18];
  const float* Ab    = (const float*)d_in[19];
  const float* skip  = (const float*)d_in[20];
  const float* ln_g  = (const float*)d_in[21];
  const float* ln_b  = (const float*)d_in[22];
  const float* Wout  = (const float*)d_in[23];
  const float* b_out = (const float*)d_in[24];
  float* out = (float*)d_out;

  static const int RSRC[NRR] = {1, 0, 2, 0};

  cudaFuncSetAttribute(gemm_h, cudaFuncAttributeMaxDynamicSharedMemorySize, GEMM_SMEM);

  // fold relation matrices, then convert all weights to fp16 transposed
  fold_weights<<<32, 256>>>(Kw, Kb, Vw, Vb, Arel, Mrel);
  conv_weights<<<dim3(64, NMATS), 256>>>(Win, Qw, Aw, Wout);

  // CSR build
  csr_zero<<<TOTSEG/256, 256>>>();
  csr_count<<<TOTEDGE/256, 256>>>(e0, e1, e2, e3);
  csr_scan1<<<TOTSEG/256, 256>>>();
  csr_scan2<<<1, 256>>>();
  csr_scan3<<<TOTSEG/256, 256>>>();
  csr_fill<<<TOTEDGE/256, 256>>>(e0, e1, e2, e3);

  // input projections
  {
    GemmBatch b = {};
    for (int t = 0; t < NT; t++)
      b.j[t] = JB(x[t], -1, 0, t, b_in + t*HIDDIM, -1, 0,
                  nullptr, ID_H, (long long)t*NXH, 0, 0, 0);
    gemm_h<<<dim3(128, 3), 512, GEMM_SMEM>>>(b, ln_g, ln_b, skip);
  }

  for (int l = 0; l < NLL; l++) {
    // Q (3) + Krel (4) + Vrel (4) batched
    {
      GemmBatch b = {};
      int n = 0;
      for (int t = 0; t < NT; t++) {
        int wi = l*NT + t;
        b.j[n++] = JB(nullptr, ID_H, (long long)t*NXH, 3 + wi, Qb + (size_t)wi*HIDDIM, -1, 0,
                      nullptr, ID_Q, (long long)t*NXH, 0, 0, 0);
      }
      for (int r = 0; r < NRR; r++) {
        int fo = l*NRR + r;
        b.j[n++] = JB(nullptr, ID_H, (long long)RSRC[r]*NXH, 15 + fo,
                      nullptr, ID_BF, (long long)fo*HIDDIM,
                      nullptr, ID_KREL, (long long)r*NXH, 0, 0, 0);
      }
      for (int r = 0; r < NRR; r++) {
        int fo = l*NRR + r;
        b.j[n++] = JB(nullptr, ID_H, (long long)RSRC[r]*NXH, 31 + fo,
                      nullptr, ID_BF, (long long)(NLL*NRR + fo)*HIDDIM,
                      nullptr, ID_MREL, (long long)r*NXH, 0, 0, 0);
      }
      gemm_h<<<dim3(128, 11), 512, GEMM_SMEM>>>(b, ln_g, ln_b, skip);
    }
    // fused attention
    attn_fused<<<dim3(NN/8, NT), 256>>>(e0, e1, e2, e3, Prel, l);
    // A-linear + gated skip + residual + LN (fused epilogue)
    {
      GemmBatch b = {};
      for (int t = 0; t < NT; t++) {
        int wi = l*NT + t;
        b.j[t] = JB(nullptr, ID_AGG, (long long)t*NXH, 47 + wi, Ab + (size_t)wi*HIDDIM, -1, 0,
                    nullptr, -1, 0, 1, wi, t);
      }
      gemm_h<<<dim3(128, 3), 512, GEMM_SMEM>>>(b, ln_g, ln_b, skip);
    }
  }

  // output projections
  {
    GemmBatch b = {};
    for (int t = 0; t < NT; t++)
      b.j[t] = JB(nullptr, ID_H, (long long)t*NXH, 59 + t, b_out + t*HIDDIM, -1, 0,
                  out + (size_t)t*NXH, -1, 0, 0, 0, 0);
    gemm_h<<<dim3(128, 3), 512, GEMM_SMEM>>>(b, ln_g, ln_b, skip);
  }
}

// round 7
// speedup vs baseline: 4.2081x; 1.0332x over previous
#include <cuda_runtime.h>
#include <cuda_fp16.h>
#include <math.h>
#include <stdint.h>

#define NN 16384
#define HIDDIM 256
#define NHD 8
#define DD 32
#define NE 65536
#define NT 3
#define NRR 4
#define NLL 4
#define NXH (NN*HIDDIM)
#define TOTSEG (NT*NN)
#define TOTEDGE (NRR*NE)
#define MAXDEG 128
#define NMATS 62

// ---------------- device scratch (allocation-free) ----------------
__device__ float g_h[NT*NXH];
__device__ float g_q[NT*NXH];
__device__ __half g_krelh[NRR*NXH];
__device__ __half g_mrelh[NRR*NXH];
__device__ float g_agg[NT*NXH];
__device__ float g_wf[2*NLL*NRR*HIDDIM*HIDDIM];
__device__ float g_bf[2*NLL*NRR*HIDDIM];
__device__ __half g_wh[NMATS*HIDDIM*HIDDIM];   // all weights, fp16, transposed [n][k]
// CSR
__device__ int g_cnt[TOTSEG];
__device__ int g_off[TOTSEG+1];
__device__ int g_pos[TOTSEG];
__device__ int g_bsum[256];
__device__ int g_elist[TOTEDGE];

#define ID_H 0
#define ID_Q 1
#define ID_AGG 2
#define ID_BF 3

__device__ __forceinline__ float* devbuf(int id) {
  switch (id) {
    case ID_H: return g_h; case ID_Q: return g_q;
    case ID_AGG: return g_agg; default: return g_bf;
  }
}

__device__ __forceinline__ float gelu_t(float x) {
  float x3 = x*x*x;
  return 0.5f*x*(1.0f + tanhf(0.7978845608028654f*(x + 0.044715f*x3)));
}

__device__ __forceinline__ uint32_t smem_u32(const void* p) {
  uint32_t a;
  asm("{ .reg .u64 t; cvta.to.shared.u64 t, %1; cvt.u32.u64 %0, t; }" : "=r"(a) : "l"(p));
  return a;
}

__device__ __forceinline__ void mma_f16(float* c, const uint32_t* a, const uint32_t* b) {
  asm volatile(
      "mma.sync.aligned.m16n8k16.row.col.f32.f16.f16.f32 "
      "{%0,%1,%2,%3}, {%4,%5,%6,%7}, {%8,%9}, {%0,%1,%2,%3};"
      : "+f"(c[0]), "+f"(c[1]), "+f"(c[2]), "+f"(c[3])
      : "r"(a[0]), "r"(a[1]), "r"(a[2]), "r"(a[3]), "r"(b[0]), "r"(b[1]));
}

// ================= weight convert+transpose: f32 [k][n] -> fp16 [n][k] =================
// 0..2 Win[t], 3..14 Qw, 15..30 wfK, 31..46 wfV, 47..58 Aw, 59..61 Wout
__global__ void __launch_bounds__(256) conv_weights(
    const float* __restrict__ Win, const float* __restrict__ Qw,
    const float* __restrict__ Aw,  const float* __restrict__ Wout)
{
  int m = blockIdx.y;
  const float* W;
  if (m < 3)        W = Win  + (size_t)m*65536;
  else if (m < 15)  W = Qw   + (size_t)(m-3)*65536;
  else if (m < 47)  W = g_wf + (size_t)(m-15)*65536;
  else if (m < 59)  W = Aw   + (size_t)(m-47)*65536;
  else              W = Wout + (size_t)(m-59)*65536;
  __half* Wt = g_wh + (size_t)m*65536;

  int tn = (blockIdx.x & 7) * 32;
  int tk = (blockIdx.x >> 3) * 32;
  __shared__ __half tile[32][33];
  int tid = threadIdx.x;
  #pragma unroll
  for (int j = 0; j < 4; j++) {
    int idx = tid + j*256;
    int kk = idx >> 5, nn = idx & 31;
    tile[kk][nn] = __float2half_rn(W[(size_t)(tk + kk)*HIDDIM + tn + nn]);
  }
  __syncthreads();
  #pragma unroll
  for (int j = 0; j < 4; j++) {
    int idx = tid + j*256;
    int nn = idx >> 5, kk = idx & 31;
    Wt[(size_t)(tn + nn)*HIDDIM + tk + kk] = tile[kk][nn];
  }
}

// ================= unified fp16 GEMM =================
// mode 0: bias -> float C.  mode 1: bias+skip+residual+LN -> g_h.  mode 2: bias -> half C.
struct GemmJob {
  const float* Aext; int Aid; long long Aoff;
  int widx;
  const float* Bext; int Bid; long long Boff;
  float* Cext; int Cid; long long Coff;
  __half* Ch;                              // mode 2 output
  int mode;
  int wi; int t;
};
struct GemmBatch { GemmJob j[12]; };

#define AP 40
#define BP 40
#define ASZH (128*AP)
#define BSZH (256*BP)
#define GEMM_SMEM ((2*ASZH + 2*BSZH)*2)

__global__ void __launch_bounds__(512, 1) gemm_h(GemmBatch batch,
    const float* __restrict__ ln_g, const float* __restrict__ ln_b,
    const float* __restrict__ skipv)
{
  const GemmJob jb = batch.j[blockIdx.y];
  const float* A = jb.Aext ? jb.Aext : (const float*)(devbuf(jb.Aid) + jb.Aoff);
  const __half* Wt = g_wh + (size_t)jb.widx*65536;
  const float* bias = jb.Bext ? jb.Bext : (const float*)(devbuf(jb.Bid) + jb.Boff);
  const int m0 = blockIdx.x * 128;

  extern __shared__ __half smh[];
  __half* As = smh;
  __half* Bs = smh + 2*ASZH;
  const uint32_t sB = smem_u32(Bs);
  __shared__ float ps[128][4], pq[128][4];
  __shared__ float rmu[128], rrs[128];

  const int tid = threadIdx.x, lane = tid & 31, wid = tid >> 5;
  const int quad = lane >> 2, tc = lane & 3;
  const int wm = (wid & 3) * 32, wn = (wid >> 2) * 64;
  const int wnix = wid >> 2;

  float acc[2][8][4];
  #pragma unroll
  for (int mt = 0; mt < 2; mt++)
    #pragma unroll
    for (int nt = 0; nt < 8; nt++)
      #pragma unroll
      for (int i = 0; i < 4; i++) acc[mt][nt][i] = 0.f;

  const int arow = tid >> 3, aseg = tid & 7;
  float4 areg0, areg1;
  auto ldA = [&](int k0) {
    areg0 = *(const float4*)(A + (size_t)(m0 + arow)*HIDDIM + k0 + aseg*4);
    areg1 = *(const float4*)(A + (size_t)(m0 + arow + 64)*HIDDIM + k0 + aseg*4);
  };
  auto stA = [&](int buf) {
    __half2 h01 = __floats2half2_rn(areg0.x, areg0.y);
    __half2 h23 = __floats2half2_rn(areg0.z, areg0.w);
    uint2 pk; pk.x = *(uint32_t*)&h01; pk.y = *(uint32_t*)&h23;
    *(uint2*)(As + buf*ASZH + arow*AP + aseg*4) = pk;
    h01 = __floats2half2_rn(areg1.x, areg1.y);
    h23 = __floats2half2_rn(areg1.z, areg1.w);
    pk.x = *(uint32_t*)&h01; pk.y = *(uint32_t*)&h23;
    *(uint2*)(As + buf*ASZH + (arow + 64)*AP + aseg*4) = pk;
  };
  auto issueB = [&](int buf, int k0) {
    #pragma unroll
    for (int j = 0; j < 2; j++) {
      int idx = tid + j*512;
      int n = idx >> 2, seg = idx & 3;
      const __half* src = Wt + (size_t)n*HIDDIM + k0 + seg*8;
      uint32_t dst = sB + (uint32_t)(buf*BSZH + n*BP + seg*8)*2u;
      asm volatile("cp.async.cg.shared.global [%0], [%1], 16;" :: "r"(dst), "l"(src) : "memory");
    }
    asm volatile("cp.async.commit_group;" ::: "memory");
  };

  ldA(0);
  issueB(0, 0);

  for (int ch = 0; ch < 8; ch++) {
    int buf = ch & 1;
    stA(buf);
    if (ch < 7) { ldA((ch + 1)*32); issueB((ch + 1) & 1, (ch + 1)*32); }
    if (ch < 7) asm volatile("cp.async.wait_group 1;" ::: "memory");
    else        asm volatile("cp.async.wait_group 0;" ::: "memory");
    __syncthreads();

    const uint32_t* A32 = (const uint32_t*)(As + buf*ASZH);
    const uint32_t* B32 = (const uint32_t*)(Bs + buf*BSZH);
    #pragma unroll
    for (int s = 0; s < 2; s++) {
      const int kh = s*8;
      uint32_t a[2][4], b[8][2];
      #pragma unroll
      for (int mt = 0; mt < 2; mt++) {
        int r = wm + mt*16 + quad;
        a[mt][0] = A32[r*(AP/2) + kh + tc];
        a[mt][1] = A32[(r+8)*(AP/2) + kh + tc];
        a[mt][2] = A32[r*(AP/2) + kh + 4 + tc];
        a[mt][3] = A32[(r+8)*(AP/2) + kh + 4 + tc];
      }
      #pragma unroll
      for (int nt = 0; nt < 8; nt++) {
        int n = wn + nt*8 + quad;
        b[nt][0] = B32[n*(BP/2) + kh + tc];
        b[nt][1] = B32[n*(BP/2) + kh + 4 + tc];
      }
      #pragma unroll
      for (int mt = 0; mt < 2; mt++)
        #pragma unroll
        for (int nt = 0; nt < 8; nt++)
          mma_f16(acc[mt][nt], a[mt], b[nt]);
    }
    __syncthreads();
  }

  if (jb.mode == 0) {
    float* C = jb.Cext ? jb.Cext : (devbuf(jb.Cid) + jb.Coff);
    #pragma unroll
    for (int nt = 0; nt < 8; nt++) {
      int cix = wn + nt*8 + tc*2;
      float2 bv = *(const float2*)(bias + cix);
      #pragma unroll
      for (int mt = 0; mt < 2; mt++) {
        int r = m0 + wm + mt*16 + quad;
        float2 o0; o0.x = acc[mt][nt][0] + bv.x; o0.y = acc[mt][nt][1] + bv.y;
        float2 o1; o1.x = acc[mt][nt][2] + bv.x; o1.y = acc[mt][nt][3] + bv.y;
        *(float2*)(C + (size_t)r*HIDDIM + cix) = o0;
        *(float2*)(C + (size_t)(r+8)*HIDDIM + cix) = o1;
      }
    }
  } else if (jb.mode == 2) {
    __half* C = jb.Ch;
    #pragma unroll
    for (int nt = 0; nt < 8; nt++) {
      int cix = wn + nt*8 + tc*2;
      float2 bv = *(const float2*)(bias + cix);
      #pragma unroll
      for (int mt = 0; mt < 2; mt++) {
        int r = m0 + wm + mt*16 + quad;
        __half2 o0 = __floats2half2_rn(acc[mt][nt][0] + bv.x, acc[mt][nt][1] + bv.y);
        __half2 o1 = __floats2half2_rn(acc[mt][nt][2] + bv.x, acc[mt][nt][3] + bv.y);
        *(__half2*)(C + (size_t)r*HIDDIM + cix) = o0;
        *(__half2*)(C + (size_t)(r+8)*HIDDIM + cix) = o1;
      }
    }
  } else {
    const int wi = jb.wi;
    const float* lg = ln_g + (size_t)wi*HIDDIM;
    const float* lb = ln_b + (size_t)wi*HIDDIM;
    float* H = g_h + (size_t)jb.t*NXH;
    const float ag = 1.f/(1.f + expf(-skipv[wi]));

    #pragma unroll
    for (int mt = 0; mt < 2; mt++) {
      #pragma unroll
      for (int half = 0; half < 2; half++) {
        int rloc = wm + mt*16 + quad + half*8;
        const float* hrow = H + (size_t)(m0 + rloc)*HIDDIM;
        float s = 0.f, q = 0.f;
        #pragma unroll
        for (int nt = 0; nt < 8; nt++) {
          int col = wn + nt*8 + tc*2;
          float2 bv = *(const float2*)(bias + col);
          float2 hv = *(const float2*)(hrow + col);
          float p0 = acc[mt][nt][half*2+0] + bv.x;
          float p1 = acc[mt][nt][half*2+1] + bv.y;
          float y0 = ag*p0 + (1.f - ag)*hv.x + hv.x;
          float y1 = ag*p1 + (1.f - ag)*hv.y + hv.y;
          acc[mt][nt][half*2+0] = y0;
          acc[mt][nt][half*2+1] = y1;
          s += y0 + y1; q += y0*y0 + y1*y1;
        }
        s += __shfl_xor_sync(~0u, s, 1); q += __shfl_xor_sync(~0u, q, 1);
        s += __shfl_xor_sync(~0u, s, 2); q += __shfl_xor_sync(~0u, q, 2);
        if (tc == 0) { ps[rloc][wnix] = s; pq[rloc][wnix] = q; }
      }
    }
    __syncthreads();
    if (tid < 128) {
      float s = ps[tid][0] + ps[tid][1] + ps[tid][2] + ps[tid][3];
      float q = pq[tid][0] + pq[tid][1] + pq[tid][2] + pq[tid][3];
      float mu = s*(1.f/256.f);
      float var = q*(1.f/256.f) - mu*mu;
      rmu[tid] = mu;
      rrs[tid] = rsqrtf(var + 1e-5f);
    }
    __syncthreads();
    #pragma unroll
    for (int mt = 0; mt < 2; mt++) {
      #pragma unroll
      for (int half = 0; half < 2; half++) {
        int rloc = wm + mt*16 + quad + half*8;
        float mu = rmu[rloc], rs = rrs[rloc];
        float* hrow = H + (size_t)(m0 + rloc)*HIDDIM;
        #pragma unroll
        for (int nt = 0; nt < 8; nt++) {
          int col = wn + nt*8 + tc*2;
          float2 gv = *(const float2*)(lg + col);
          float2 bv2 = *(const float2*)(lb + col);
          float2 o;
          o.x = (acc[mt][nt][half*2+0] - mu)*rs*gv.x + bv2.x;
          o.y = (acc[mt][nt][half*2+1] - mu)*rs*gv.y + bv2.y;
          *(float2*)(hrow + col) = o;
        }
      }
    }
  }
}

// ================= fold relation matrices into K/V weights =================
__global__ void __launch_bounds__(256) fold_weights(
    const float* __restrict__ Kw, const float* __restrict__ Kb,
    const float* __restrict__ Vw, const float* __restrict__ Vb,
    const float* __restrict__ Arel, const float* __restrict__ Mrel)
{
  int b = blockIdx.x;
  int r = b & 3, l = (b >> 2) & 3, kv = b >> 4;
  const int RSRC[4] = {1, 0, 2, 0};
  int s = RSRC[r];
  const float* W   = (kv ? Vw : Kw) + (size_t)(l*NT + s)*HIDDIM*HIDDIM;
  const float* bb  = (kv ? Vb : Kb) + (size_t)(l*NT + s)*HIDDIM;
  const float* Rel = (kv ? Mrel : Arel) + (size_t)(l*NRR + r)*NHD*DD*DD;
  float* Wo = g_wf + (size_t)(kv*NLL*NRR + l*NRR + r)*HIDDIM*HIDDIM;
  float* bo = g_bf + (size_t)(kv*NLL*NRR + l*NRR + r)*HIDDIM;

  __shared__ float Rs[NHD*DD*DD];
  int tid = threadIdx.x;
  for (int i = tid; i < NHD*DD*DD; i += 256) Rs[i] = Rel[i];
  __syncthreads();

  const float* wrow = W + (size_t)tid*HIDDIM;
  float* worow = Wo + (size_t)tid*HIDDIM;
  for (int h = 0; h < NHD; h++) {
    float xv[DD];
    #pragma unroll
    for (int d = 0; d < DD; d++) xv[d] = wrow[h*DD + d];
    for (int e = 0; e < DD; e++) {
      float acc = 0.f;
      #pragma unroll
      for (int d = 0; d < DD; d++) acc += xv[d] * Rs[(h*DD + d)*DD + e];
      worow[h*DD + e] = acc;
    }
  }
  {
    int h = tid >> 5, e = tid & 31;
    float acc = 0.f;
    #pragma unroll
    for (int d = 0; d < DD; d++) acc += bb[h*DD + d] * Rs[(h*DD + d)*DD + e];
    bo[tid] = acc;
  }
}

// ================= CSR build =================
__device__ __forceinline__ int rdst_of(int r) { return (r == 1) ? 2 : (r == 2) ? 1 : 0; }

__global__ void csr_zero() {
  int i = blockIdx.x*256 + threadIdx.x;
  if (i < TOTSEG) g_cnt[i] = 0;
}
__global__ void csr_count(const int* __restrict__ e0, const int* __restrict__ e1,
                          const int* __restrict__ e2, const int* __restrict__ e3) {
  int idx = blockIdx.x*256 + threadIdx.x;
  int r = idx >> 16, e = idx & 0xFFFF;
  const int* ep = (r == 0) ? e0 : (r == 1) ? e1 : (r == 2) ? e2 : e3;
  int dst = ep[NE + e];
  atomicAdd(&g_cnt[rdst_of(r)*NN + dst], 1);
}
__global__ void csr_scan1() {
  int gid = blockIdx.x*256 + threadIdx.x;
  int v = g_cnt[gid];
  int lane = threadIdx.x & 31, w = threadIdx.x >> 5;
  int x = v;
  #pragma unroll
  for (int o = 1; o < 32; o <<= 1) { int n = __shfl_up_sync(~0u, x, o); if (lane >= o) x += n; }
  __shared__ int ws[8];
  if (lane == 31) ws[w] = x;
  __syncthreads();
  int prefix = 0;
  for (int i = 0; i < w; i++) prefix += ws[i];
  int excl = prefix + x - v;
  g_off[gid] = excl;
  if (threadIdx.x == 255) g_bsum[blockIdx.x] = excl + v;
}
__global__ void csr_scan2() {
  int v = (threadIdx.x < 192) ? g_bsum[threadIdx.x] : 0;
  int lane = threadIdx.x & 31, w = threadIdx.x >> 5;
  int x = v;
  #pragma unroll
  for (int o = 1; o < 32; o <<= 1) { int n = __shfl_up_sync(~0u, x, o); if (lane >= o) x += n; }
  __shared__ int ws[8];
  if (lane == 31) ws[w] = x;
  __syncthreads();
  int prefix = 0;
  for (int i = 0; i < w; i++) prefix += ws[i];
  if (threadIdx.x < 192) g_bsum[threadIdx.x] = prefix + x - v;
}
__global__ void csr_scan3() {
  int gid = blockIdx.x*256 + threadIdx.x;
  int o = g_off[gid] + g_bsum[blockIdx.x];
  g_off[gid] = o;
  g_pos[gid] = o;
  if (gid == 0) g_off[TOTSEG] = TOTEDGE;
}
__global__ void csr_fill(const int* __restrict__ e0, const int* __restrict__ e1,
                         const int* __restrict__ e2, const int* __restrict__ e3) {
  int idx = blockIdx.x*256 + threadIdx.x;
  int r = idx >> 16, e = idx & 0xFFFF;
  const int* ep = (r == 0) ? e0 : (r == 1) ? e1 : (r == 2) ? e2 : e3;
  int dst = ep[NE + e];
  int pos = atomicAdd(&g_pos[rdst_of(r)*NN + dst], 1);
  g_elist[pos] = (r << 16) | e;
}

// ================= fused attention (fp16 krel/mrel gathers) =================
__global__ void __launch_bounds__(256) attn_fused(
    const int* __restrict__ e0, const int* __restrict__ e1,
    const int* __restrict__ e2, const int* __restrict__ e3,
    const float* __restrict__ Prel, int l)
{
  __shared__ float ssc[8][MAXDEG][8];
  const int t = blockIdx.y;
  const int wid = threadIdx.x >> 5, lane = threadIdx.x & 31;
  const int node = blockIdx.x*8 + wid;
  const int base = t*NN + node;
  const int off0 = g_off[base];
  const int deg  = g_off[base + 1] - off0;

  // q floats [8*lane, 8*lane+8) -> matches half-lane layout; head = lane>>2
  const float4* qrow = (const float4*)(g_q + (size_t)t*NXH + (size_t)node*HIDDIM);
  const float4 q0 = qrow[2*lane], q1 = qrow[2*lane + 1];
  const float scale = 0.17677669529663687f;
  const int myh = lane >> 2;

  float mx = -INFINITY;
  for (int i = 0; i < deg; i++) {
    int p = g_elist[off0 + i];
    int r = p >> 16, e = p & 0xFFFF;
    const int* ep = (r == 0) ? e0 : (r == 1) ? e1 : (r == 2) ? e2 : e3;
    int src = ep[e];
    const uint4* kr = (const uint4*)(g_krelh + (size_t)r*NXH + (size_t)src*HIDDIM);
    uint4 kv = kr[lane];                 // 8 halves
    float2 k0 = __half22float2(*(__half2*)&kv.x);
    float2 k1 = __half22float2(*(__half2*)&kv.y);
    float2 k2 = __half22float2(*(__half2*)&kv.z);
    float2 k3 = __half22float2(*(__half2*)&kv.w);
    float pp = q0.x*k0.x + q0.y*k0.y + q0.z*k1.x + q0.w*k1.y
             + q1.x*k2.x + q1.y*k2.y + q1.z*k3.x + q1.w*k3.y;
    pp += __shfl_xor_sync(~0u, pp, 1);
    pp += __shfl_xor_sync(~0u, pp, 2);   // lanes 4h..4h+3 now hold head h score
    float s = __shfl_sync(~0u, pp, lane*4);  // lane<8 reads head=lane
    if (lane < 8) {
      s *= Prel[(size_t)(l*NRR + r)*NHD + lane] * scale;
      ssc[wid][i][lane] = s;
      mx = fmaxf(mx, s);
    }
  }
  float den = 0.f;
  if (lane < 8) {
    for (int i = 0; i < deg; i++) {
      float ex = expf(ssc[wid][i][lane] - mx);
      ssc[wid][i][lane] = ex;
      den += ex;
    }
  }
  float inv = (lane < 8) ? 1.f/fmaxf(den, 1e-16f) : 0.f;
  float myinv = __shfl_sync(~0u, inv, myh);
  __syncwarp();

  float a0 = 0, a1 = 0, a2 = 0, a3 = 0, a4 = 0, a5 = 0, a6 = 0, a7 = 0;
  for (int i = 0; i < deg; i++) {
    int p = g_elist[off0 + i];
    int r = p >> 16, e = p & 0xFFFF;
    const int* ep = (r == 0) ? e0 : (r == 1) ? e1 : (r == 2) ? e2 : e3;
    int src = ep[e];
    const uint4* mr = (const uint4*)(g_mrelh + (size_t)r*NXH + (size_t)src*HIDDIM);
    float al = ssc[wid][i][myh] * myinv;
    uint4 mv = mr[lane];
    float2 m0 = __half22float2(*(__half2*)&mv.x);
    float2 m1 = __half22float2(*(__half2*)&mv.y);
    float2 m2 = __half22float2(*(__half2*)&mv.z);
    float2 m3 = __half22float2(*(__half2*)&mv.w);
    a0 += al*m0.x; a1 += al*m0.y; a2 += al*m1.x; a3 += al*m1.y;
    a4 += al*m2.x; a5 += al*m2.y; a6 += al*m3.x; a7 += al*m3.y;
  }
  float4* outr = (float4*)(g_agg + (size_t)t*NXH + (size_t)node*HIDDIM);
  float4 o0, o1;
  o0.x = gelu_t(a0); o0.y = gelu_t(a1); o0.z = gelu_t(a2); o0.w = gelu_t(a3);
  o1.x = gelu_t(a4); o1.y = gelu_t(a5); o1.z = gelu_t(a6); o1.w = gelu_t(a7);
  outr[2*lane] = o0; outr[2*lane + 1] = o1;
}

// ================= host orchestration =================
static inline GemmJob JB(const float* Aext, int Aid, long long Aoff, int widx,
                         const float* Bext, int Bid, long long Boff,
                         float* Cext, int Cid, long long Coff,
                         __half* Ch, int mode, int wi, int t) {
  GemmJob j; j.Aext=Aext; j.Aid=Aid; j.Aoff=Aoff; j.widx=widx;
  j.Bext=Bext; j.Bid=Bid; j.Boff=Boff; j.Cext=Cext; j.Cid=Cid; j.Coff=Coff;
  j.Ch=Ch; j.mode=mode; j.wi=wi; j.t=t;
  return j;
}

extern "C" void kernel_launch(void* const* d_in, const int* in_sizes, int n_in,
                              void* d_out, int out_size) {
  const float* x[NT]  = {(const float*)d_in[0], (const float*)d_in[1], (const float*)d_in[2]};
  const int* e0 = (const int*)d_in[3];
  const int* e1 = (const int*)d_in[4];
  const int* e2 = (const int*)d_in[5];
  const int* e3 = (const int*)d_in[6];
  const float* Win   = (const float*)d_in[7];
  const float* b_in  = (const float*)d_in[8];
  const float* Kw    = (const float*)d_in[9];
  const float* Kb    = (const float*)d_in[10];
  const float* Qw    = (const float*)d_in[11];
  const float* Qb    = (const float*)d_in[12];
  const float* Vw    = (const float*)d_in[13];
  const float* Vb    = (const float*)d_in[14];
  const float* Arel  = (const float*)d_in[15];
  const float* Mrel  = (const float*)d_in[16];
  const float* Prel  = (const float*)d_in[17];
  const float* Aw    = (const float*)d_in[18];
  const float* Ab    = (const float*)d_in[19];
  const float* skip  = (const float*)d_in[20];
  const float* ln_g  = (const float*)d_in[21];
  const float* ln_b  = (const float*)d_in[22];
  const float* Wout  = (const float*)d_in[23];
  const float* b_out = (const float*)d_in[24];
  float* out = (float*)d_out;

  static const int RSRC[NRR] = {1, 0, 2, 0};

  __half* krelh = nullptr; __half* mrelh = nullptr;
  cudaGetSymbolAddress((void**)&krelh, g_krelh);
  cudaGetSymbolAddress((void**)&mrelh, g_mrelh);

  cudaFuncSetAttribute(gemm_h, cudaFuncAttributeMaxDynamicSharedMemorySize, GEMM_SMEM);

  fold_weights<<<32, 256>>>(Kw, Kb, Vw, Vb, Arel, Mrel);
  conv_weights<<<dim3(64, NMATS), 256>>>(Win, Qw, Aw, Wout);

  csr_zero<<<TOTSEG/256, 256>>>();
  csr_count<<<TOTEDGE/256, 256>>>(e0, e1, e2, e3);
  csr_scan1<<<TOTSEG/256, 256>>>();
  csr_scan2<<<1, 256>>>();
  csr_scan3<<<TOTSEG/256, 256>>>();
  csr_fill<<<TOTEDGE/256, 256>>>(e0, e1, e2, e3);

  // input projections
  {
    GemmBatch b = {};
    for (int t = 0; t < NT; t++)
      b.j[t] = JB(x[t], -1, 0, t, b_in + t*HIDDIM, -1, 0,
                  nullptr, ID_H, (long long)t*NXH, nullptr, 0, 0, 0);
    gemm_h<<<dim3(128, 3), 512, GEMM_SMEM>>>(b, ln_g, ln_b, skip);
  }

  for (int l = 0; l < NLL; l++) {
    // Q (3, fp32 out) + Krel (4, fp16 out) + Vrel (4, fp16 out)
    {
      GemmBatch b = {};
      int n = 0;
      for (int t = 0; t < NT; t++) {
        int wi = l*NT + t;
        b.j[n++] = JB(nullptr, ID_H, (long long)t*NXH, 3 + wi, Qb + (size_t)wi*HIDDIM, -1, 0,
                      nullptr, ID_Q, (long long)t*NXH, nullptr, 0, 0, 0);
      }
      for (int r = 0; r < NRR; r++) {
        int fo = l*NRR + r;
        b.j[n++] = JB(nullptr, ID_H, (long long)RSRC[r]*NXH, 15 + fo,
                      nullptr, ID_BF, (long long)fo*HIDDIM,
                      nullptr, -1, 0, krelh + (size_t)r*NXH, 2, 0, 0);
      }
      for (int r = 0; r < NRR; r++) {
        int fo = l*NRR + r;
        b.j[n++] = JB(nullptr, ID_H, (long long)RSRC[r]*NXH, 31 + fo,
                      nullptr, ID_BF, (long long)(NLL*NRR + fo)*HIDDIM,
                      nullptr, -1, 0, mrelh + (size_t)r*NXH, 2, 0, 0);
      }
      gemm_h<<<dim3(128, 11), 512, GEMM_SMEM>>>(b, ln_g, ln_b, skip);
    }
    // fused attention
    attn_fused<<<dim3(NN/8, NT), 256>>>(e0, e1, e2, e3, Prel, l);
    // A-linear + gated skip + residual + LN
    {
      GemmBatch b = {};
      for (int t = 0; t < NT; t++) {
        int wi = l*NT + t;
        b.j[t] = JB(nullptr, ID_AGG, (long long)t*NXH, 47 + wi, Ab + (size_t)wi*HIDDIM, -1, 0,
                    nullptr, -1, 0, nullptr, 1, wi, t);
      }
      gemm_h<<<dim3(128, 3), 512, GEMM_SMEM>>>(b, ln_g, ln_b, skip);
    }
  }

  // output projections
  {
    GemmBatch b = {};
    for (int t = 0; t < NT; t++)
      b.j[t] = JB(nullptr, ID_H, (long long)t*NXH, 59 + t, b_out + t*HIDDIM, -1, 0,
                  out + (size_t)t*NXH, -1, 0, nullptr, 0, 0, 0);
    gemm_h<<<dim3(128, 3), 512, GEMM_SMEM>>>(b, ln_g, ln_b, skip);
  }
}

// round 8
// speedup vs baseline: 4.3361x; 1.0304x over previous
#include <cuda_runtime.h>
#include <cuda_fp16.h>
#include <math.h>
#include <stdint.h>

#define NN 16384
#define HIDDIM 256
#define NHD 8
#define DD 32
#define NE 65536
#define NT 3
#define NRR 4
#define NLL 4
#define NXH (NN*HIDDIM)
#define TOTSEG (NT*NN)
#define TOTEDGE (NRR*NE)
#define MAXDEG 128
#define NMATS 62

// ---------------- device scratch (allocation-free) ----------------
__device__ float g_h[NT*NXH];
__device__ float g_q[NT*NXH];
__device__ __half g_krelh[NRR*NXH];
__device__ __half g_mrelh[NRR*NXH];
__device__ float g_agg[NT*NXH];
__device__ float g_wf[2*NLL*NRR*HIDDIM*HIDDIM];
__device__ float g_bf[2*NLL*NRR*HIDDIM];
__device__ __half g_wh[NMATS*HIDDIM*HIDDIM];
// CSR
__device__ int g_cnt[TOTSEG];
__device__ int g_off[TOTSEG+1];
__device__ int g_pos[TOTSEG];
__device__ int g_bsum[256];
__device__ int g_elist[TOTEDGE];

#define ID_H 0
#define ID_Q 1
#define ID_AGG 2
#define ID_BF 3

__device__ __forceinline__ float* devbuf(int id) {
  switch (id) {
    case ID_H: return g_h; case ID_Q: return g_q;
    case ID_AGG: return g_agg; default: return g_bf;
  }
}

__device__ __forceinline__ float gelu_t(float x) {
  float x3 = x*x*x;
  return 0.5f*x*(1.0f + tanhf(0.7978845608028654f*(x + 0.044715f*x3)));
}

__device__ __forceinline__ uint32_t smem_u32(const void* p) {
  uint32_t a;
  asm("{ .reg .u64 t; cvta.to.shared.u64 t, %1; cvt.u32.u64 %0, t; }" : "=r"(a) : "l"(p));
  return a;
}

__device__ __forceinline__ void mma_f16(float* c, const uint32_t* a, const uint32_t* b) {
  asm volatile(
      "mma.sync.aligned.m16n8k16.row.col.f32.f16.f16.f32 "
      "{%0,%1,%2,%3}, {%4,%5,%6,%7}, {%8,%9}, {%0,%1,%2,%3};"
      : "+f"(c[0]), "+f"(c[1]), "+f"(c[2]), "+f"(c[3])
      : "r"(a[0]), "r"(a[1]), "r"(a[2]), "r"(a[3]), "r"(b[0]), "r"(b[1]));
}

// ================= weight convert+transpose: f32 [k][n] -> fp16 [n][k] =================
__global__ void __launch_bounds__(256) conv_weights(
    const float* __restrict__ Win, const float* __restrict__ Qw,
    const float* __restrict__ Aw,  const float* __restrict__ Wout)
{
  int m = blockIdx.y;
  const float* W;
  if (m < 3)        W = Win  + (size_t)m*65536;
  else if (m < 15)  W = Qw   + (size_t)(m-3)*65536;
  else if (m < 47)  W = g_wf + (size_t)(m-15)*65536;
  else if (m < 59)  W = Aw   + (size_t)(m-47)*65536;
  else              W = Wout + (size_t)(m-59)*65536;
  __half* Wt = g_wh + (size_t)m*65536;

  int tn = (blockIdx.x & 7) * 32;
  int tk = (blockIdx.x >> 3) * 32;
  __shared__ __half tile[32][33];
  int tid = threadIdx.x;
  #pragma unroll
  for (int j = 0; j < 4; j++) {
    int idx = tid + j*256;
    int kk = idx >> 5, nn = idx & 31;
    tile[kk][nn] = __float2half_rn(W[(size_t)(tk + kk)*HIDDIM + tn + nn]);
  }
  __syncthreads();
  #pragma unroll
  for (int j = 0; j < 4; j++) {
    int idx = tid + j*256;
    int nn = idx >> 5, kk = idx & 31;
    Wt[(size_t)(tn + nn)*HIDDIM + tk + kk] = tile[kk][nn];
  }
}

// ================= unified fp16 GEMM: 256 threads, tile 64x256, 2 CTAs/SM =================
// mode 0: bias -> float C.  mode 1: bias+skip+residual+LN -> g_h.  mode 2: bias -> half C.
struct GemmJob {
  const float* Aext; int Aid; long long Aoff;
  int widx;
  const float* Bext; int Bid; long long Boff;
  float* Cext; int Cid; long long Coff;
  __half* Ch;
  int mode;
  int wi; int t;
};
struct GemmBatch { GemmJob j[12]; };

#define AP 40
#define BP 40
#define ASZH (64*AP)              // 2560 halves
#define BSZH (256*BP)             // 10240 halves
#define GEMM_SMEM ((2*ASZH + 2*BSZH)*2)   // 51200 bytes

__global__ void __launch_bounds__(256, 2) gemm_h(GemmBatch batch,
    const float* __restrict__ ln_g, const float* __restrict__ ln_b,
    const float* __restrict__ skipv)
{
  const GemmJob jb = batch.j[blockIdx.y];
  const float* A = jb.Aext ? jb.Aext : (const float*)(devbuf(jb.Aid) + jb.Aoff);
  const __half* Wt = g_wh + (size_t)jb.widx*65536;
  const float* bias = jb.Bext ? jb.Bext : (const float*)(devbuf(jb.Bid) + jb.Boff);
  const int m0 = blockIdx.x * 64;

  extern __shared__ __half smh[];
  __half* As = smh;                 // 2 x ASZH
  __half* Bs = smh + 2*ASZH;        // 2 x BSZH
  const uint32_t sB = smem_u32(Bs);
  __shared__ float ps[64][4], pq[64][4];
  __shared__ float rmu[64], rrs[64];

  const int tid = threadIdx.x, lane = tid & 31, wid = tid >> 5;
  const int quad = lane >> 2, tc = lane & 3;
  const int wm = (wid & 1) * 32, wn = (wid >> 1) * 64;
  const int wnix = wid >> 1;

  float acc[2][8][4];
  #pragma unroll
  for (int mt = 0; mt < 2; mt++)
    #pragma unroll
    for (int nt = 0; nt < 8; nt++)
      #pragma unroll
      for (int i = 0; i < 4; i++) acc[mt][nt][i] = 0.f;

  // A tile: 64 rows x 32 k fp32 -> fp16. Each thread: 8 contiguous floats.
  const int arow = tid >> 2, acol = (tid & 3) * 8;
  float4 areg0, areg1;
  auto ldA = [&](int k0) {
    const float* src = A + (size_t)(m0 + arow)*HIDDIM + k0 + acol;
    areg0 = *(const float4*)(src);
    areg1 = *(const float4*)(src + 4);
  };
  auto stA = [&](int buf) {
    __half2 h0 = __floats2half2_rn(areg0.x, areg0.y);
    __half2 h1 = __floats2half2_rn(areg0.z, areg0.w);
    __half2 h2 = __floats2half2_rn(areg1.x, areg1.y);
    __half2 h3 = __floats2half2_rn(areg1.z, areg1.w);
    uint4 pk; pk.x = *(uint32_t*)&h0; pk.y = *(uint32_t*)&h1;
    pk.z = *(uint32_t*)&h2; pk.w = *(uint32_t*)&h3;
    *(uint4*)(As + buf*ASZH + arow*AP + acol) = pk;
  };
  auto issueB = [&](int buf, int k0) {
    #pragma unroll
    for (int j = 0; j < 4; j++) {
      int idx = tid + j*256;
      int n = idx >> 2, seg = idx & 3;
      const __half* src = Wt + (size_t)n*HIDDIM + k0 + seg*8;
      uint32_t dst = sB + (uint32_t)(buf*BSZH + n*BP + seg*8)*2u;
      asm volatile("cp.async.cg.shared.global [%0], [%1], 16;" :: "r"(dst), "l"(src) : "memory");
    }
    asm volatile("cp.async.commit_group;" ::: "memory");
  };

  ldA(0);
  issueB(0, 0);

  for (int ch = 0; ch < 8; ch++) {
    int buf = ch & 1;
    stA(buf);
    if (ch < 7) { ldA((ch + 1)*32); issueB((ch + 1) & 1, (ch + 1)*32); }
    if (ch < 7) asm volatile("cp.async.wait_group 1;" ::: "memory");
    else        asm volatile("cp.async.wait_group 0;" ::: "memory");
    __syncthreads();

    const uint32_t* A32 = (const uint32_t*)(As + buf*ASZH);
    const uint32_t* B32 = (const uint32_t*)(Bs + buf*BSZH);
    #pragma unroll
    for (int s = 0; s < 2; s++) {
      const int kh = s*8;
      uint32_t a[2][4], b[8][2];
      #pragma unroll
      for (int mt = 0; mt < 2; mt++) {
        int r = wm + mt*16 + quad;
        a[mt][0] = A32[r*(AP/2) + kh + tc];
        a[mt][1] = A32[(r+8)*(AP/2) + kh + tc];
        a[mt][2] = A32[r*(AP/2) + kh + 4 + tc];
        a[mt][3] = A32[(r+8)*(AP/2) + kh + 4 + tc];
      }
      #pragma unroll
      for (int nt = 0; nt < 8; nt++) {
        int n = wn + nt*8 + quad;
        b[nt][0] = B32[n*(BP/2) + kh + tc];
        b[nt][1] = B32[n*(BP/2) + kh + 4 + tc];
      }
      #pragma unroll
      for (int mt = 0; mt < 2; mt++)
        #pragma unroll
        for (int nt = 0; nt < 8; nt++)
          mma_f16(acc[mt][nt], a[mt], b[nt]);
    }
    __syncthreads();
  }

  if (jb.mode == 0) {
    float* C = jb.Cext ? jb.Cext : (devbuf(jb.Cid) + jb.Coff);
    #pragma unroll
    for (int nt = 0; nt < 8; nt++) {
      int cix = wn + nt*8 + tc*2;
      float2 bv = *(const float2*)(bias + cix);
      #pragma unroll
      for (int mt = 0; mt < 2; mt++) {
        int r = m0 + wm + mt*16 + quad;
        float2 o0; o0.x = acc[mt][nt][0] + bv.x; o0.y = acc[mt][nt][1] + bv.y;
        float2 o1; o1.x = acc[mt][nt][2] + bv.x; o1.y = acc[mt][nt][3] + bv.y;
        *(float2*)(C + (size_t)r*HIDDIM + cix) = o0;
        *(float2*)(C + (size_t)(r+8)*HIDDIM + cix) = o1;
      }
    }
  } else if (jb.mode == 2) {
    __half* C = jb.Ch;
    #pragma unroll
    for (int nt = 0; nt < 8; nt++) {
      int cix = wn + nt*8 + tc*2;
      float2 bv = *(const float2*)(bias + cix);
      #pragma unroll
      for (int mt = 0; mt < 2; mt++) {
        int r = m0 + wm + mt*16 + quad;
        __half2 o0 = __floats2half2_rn(acc[mt][nt][0] + bv.x, acc[mt][nt][1] + bv.y);
        __half2 o1 = __floats2half2_rn(acc[mt][nt][2] + bv.x, acc[mt][nt][3] + bv.y);
        *(__half2*)(C + (size_t)r*HIDDIM + cix) = o0;
        *(__half2*)(C + (size_t)(r+8)*HIDDIM + cix) = o1;
      }
    }
  } else {
    const int wi = jb.wi;
    const float* lg = ln_g + (size_t)wi*HIDDIM;
    const float* lb = ln_b + (size_t)wi*HIDDIM;
    float* H = g_h + (size_t)jb.t*NXH;
    const float ag = 1.f/(1.f + expf(-skipv[wi]));

    #pragma unroll
    for (int mt = 0; mt < 2; mt++) {
      #pragma unroll
      for (int half = 0; half < 2; half++) {
        int rloc = wm + mt*16 + quad + half*8;
        const float* hrow = H + (size_t)(m0 + rloc)*HIDDIM;
        float s = 0.f, q = 0.f;
        #pragma unroll
        for (int nt = 0; nt < 8; nt++) {
          int col = wn + nt*8 + tc*2;
          float2 bv = *(const float2*)(bias + col);
          float2 hv = *(const float2*)(hrow + col);
          float p0 = acc[mt][nt][half*2+0] + bv.x;
          float p1 = acc[mt][nt][half*2+1] + bv.y;
          float y0 = ag*p0 + (1.f - ag)*hv.x + hv.x;
          float y1 = ag*p1 + (1.f - ag)*hv.y + hv.y;
          acc[mt][nt][half*2+0] = y0;
          acc[mt][nt][half*2+1] = y1;
          s += y0 + y1; q += y0*y0 + y1*y1;
        }
        s += __shfl_xor_sync(~0u, s, 1); q += __shfl_xor_sync(~0u, q, 1);
        s += __shfl_xor_sync(~0u, s, 2); q += __shfl_xor_sync(~0u, q, 2);
        if (tc == 0) { ps[rloc][wnix] = s; pq[rloc][wnix] = q; }
      }
    }
    __syncthreads();
    if (tid < 64) {
      float s = ps[tid][0] + ps[tid][1] + ps[tid][2] + ps[tid][3];
      float q = pq[tid][0] + pq[tid][1] + pq[tid][2] + pq[tid][3];
      float mu = s*(1.f/256.f);
      float var = q*(1.f/256.f) - mu*mu;
      rmu[tid] = mu;
      rrs[tid] = rsqrtf(var + 1e-5f);
    }
    __syncthreads();
    #pragma unroll
    for (int mt = 0; mt < 2; mt++) {
      #pragma unroll
      for (int half = 0; half < 2; half++) {
        int rloc = wm + mt*16 + quad + half*8;
        float mu = rmu[rloc], rs = rrs[rloc];
        float* hrow = H + (size_t)(m0 + rloc)*HIDDIM;
        #pragma unroll
        for (int nt = 0; nt < 8; nt++) {
          int col = wn + nt*8 + tc*2;
          float2 gv = *(const float2*)(lg + col);
          float2 bv2 = *(const float2*)(lb + col);
          float2 o;
          o.x = (acc[mt][nt][half*2+0] - mu)*rs*gv.x + bv2.x;
          o.y = (acc[mt][nt][half*2+1] - mu)*rs*gv.y + bv2.y;
          *(float2*)(hrow + col) = o;
        }
      }
    }
  }
}

// ================= fold relation matrices into K/V weights =================
__global__ void __launch_bounds__(256) fold_weights(
    const float* __restrict__ Kw, const float* __restrict__ Kb,
    const float* __restrict__ Vw, const float* __restrict__ Vb,
    const float* __restrict__ Arel, const float* __restrict__ Mrel)
{
  int b = blockIdx.x;
  int r = b & 3, l = (b >> 2) & 3, kv = b >> 4;
  const int RSRC[4] = {1, 0, 2, 0};
  int s = RSRC[r];
  const float* W   = (kv ? Vw : Kw) + (size_t)(l*NT + s)*HIDDIM*HIDDIM;
  const float* bb  = (kv ? Vb : Kb) + (size_t)(l*NT + s)*HIDDIM;
  const float* Rel = (kv ? Mrel : Arel) + (size_t)(l*NRR + r)*NHD*DD*DD;
  float* Wo = g_wf + (size_t)(kv*NLL*NRR + l*NRR + r)*HIDDIM*HIDDIM;
  float* bo = g_bf + (size_t)(kv*NLL*NRR + l*NRR + r)*HIDDIM;

  __shared__ float Rs[NHD*DD*DD];
  int tid = threadIdx.x;
  for (int i = tid; i < NHD*DD*DD; i += 256) Rs[i] = Rel[i];
  __syncthreads();

  const float* wrow = W + (size_t)tid*HIDDIM;
  float* worow = Wo + (size_t)tid*HIDDIM;
  for (int h = 0; h < NHD; h++) {
    float xv[DD];
    #pragma unroll
    for (int d = 0; d < DD; d++) xv[d] = wrow[h*DD + d];
    for (int e = 0; e < DD; e++) {
      float acc = 0.f;
      #pragma unroll
      for (int d = 0; d < DD; d++) acc += xv[d] * Rs[(h*DD + d)*DD + e];
      worow[h*DD + e] = acc;
    }
  }
  {
    int h = tid >> 5, e = tid & 31;
    float acc = 0.f;
    #pragma unroll
    for (int d = 0; d < DD; d++) acc += bb[h*DD + d] * Rs[(h*DD + d)*DD + e];
    bo[tid] = acc;
  }
}

// ================= CSR build =================
__device__ __forceinline__ int rdst_of(int r) { return (r == 1) ? 2 : (r == 2) ? 1 : 0; }

__global__ void csr_zero() {
  int i = blockIdx.x*256 + threadIdx.x;
  if (i < TOTSEG) g_cnt[i] = 0;
}
__global__ void csr_count(const int* __restrict__ e0, const int* __restrict__ e1,
                          const int* __restrict__ e2, const int* __restrict__ e3) {
  int idx = blockIdx.x*256 + threadIdx.x;
  int r = idx >> 16, e = idx & 0xFFFF;
  const int* ep = (r == 0) ? e0 : (r == 1) ? e1 : (r == 2) ? e2 : e3;
  int dst = ep[NE + e];
  atomicAdd(&g_cnt[rdst_of(r)*NN + dst], 1);
}
__global__ void csr_scan1() {
  int gid = blockIdx.x*256 + threadIdx.x;
  int v = g_cnt[gid];
  int lane = threadIdx.x & 31, w = threadIdx.x >> 5;
  int x = v;
  #pragma unroll
  for (int o = 1; o < 32; o <<= 1) { int n = __shfl_up_sync(~0u, x, o); if (lane >= o) x += n; }
  __shared__ int ws[8];
  if (lane == 31) ws[w] = x;
  __syncthreads();
  int prefix = 0;
  for (int i = 0; i < w; i++) prefix += ws[i];
  int excl = prefix + x - v;
  g_off[gid] = excl;
  if (threadIdx.x == 255) g_bsum[blockIdx.x] = excl + v;
}
__global__ void csr_scan2() {
  int v = (threadIdx.x < 192) ? g_bsum[threadIdx.x] : 0;
  int lane = threadIdx.x & 31, w = threadIdx.x >> 5;
  int x = v;
  #pragma unroll
  for (int o = 1; o < 32; o <<= 1) { int n = __shfl_up_sync(~0u, x, o); if (lane >= o) x += n; }
  __shared__ int ws[8];
  if (lane == 31) ws[w] = x;
  __syncthreads();
  int prefix = 0;
  for (int i = 0; i < w; i++) prefix += ws[i];
  if (threadIdx.x < 192) g_bsum[threadIdx.x] = prefix + x - v;
}
__global__ void csr_scan3() {
  int gid = blockIdx.x*256 + threadIdx.x;
  int o = g_off[gid] + g_bsum[blockIdx.x];
  g_off[gid] = o;
  g_pos[gid] = o;
  if (gid == 0) g_off[TOTSEG] = TOTEDGE;
}
__global__ void csr_fill(const int* __restrict__ e0, const int* __restrict__ e1,
                         const int* __restrict__ e2, const int* __restrict__ e3) {
  int idx = blockIdx.x*256 + threadIdx.x;
  int r = idx >> 16, e = idx & 0xFFFF;
  const int* ep = (r == 0) ? e0 : (r == 1) ? e1 : (r == 2) ? e2 : e3;
  int dst = ep[NE + e];
  int pos = atomicAdd(&g_pos[rdst_of(r)*NN + dst], 1);
  g_elist[pos] = (r << 16) | e;
}

// ================= fused attention (fp16 krel/mrel gathers) =================
__global__ void __launch_bounds__(256) attn_fused(
    const int* __restrict__ e0, const int* __restrict__ e1,
    const int* __restrict__ e2, const int* __restrict__ e3,
    const float* __restrict__ Prel, int l)
{
  __shared__ float ssc[8][MAXDEG][8];
  const int t = blockIdx.y;
  const int wid = threadIdx.x >> 5, lane = threadIdx.x & 31;
  const int node = blockIdx.x*8 + wid;
  const int base = t*NN + node;
  const int off0 = g_off[base];
  const int deg  = g_off[base + 1] - off0;

  const float4* qrow = (const float4*)(g_q + (size_t)t*NXH + (size_t)node*HIDDIM);
  const float4 q0 = qrow[2*lane], q1 = qrow[2*lane + 1];
  const float scale = 0.17677669529663687f;
  const int myh = lane >> 2;

  float mx = -INFINITY;
  for (int i = 0; i < deg; i++) {
    int p = g_elist[off0 + i];
    int r = p >> 16, e = p & 0xFFFF;
    const int* ep = (r == 0) ? e0 : (r == 1) ? e1 : (r == 2) ? e2 : e3;
    int src = ep[e];
    const uint4* kr = (const uint4*)(g_krelh + (size_t)r*NXH + (size_t)src*HIDDIM);
    uint4 kv = kr[lane];
    float2 k0 = __half22float2(*(__half2*)&kv.x);
    float2 k1 = __half22float2(*(__half2*)&kv.y);
    float2 k2 = __half22float2(*(__half2*)&kv.z);
    float2 k3 = __half22float2(*(__half2*)&kv.w);
    float pp = q0.x*k0.x + q0.y*k0.y + q0.z*k1.x + q0.w*k1.y
             + q1.x*k2.x + q1.y*k2.y + q1.z*k3.x + q1.w*k3.y;
    pp += __shfl_xor_sync(~0u, pp, 1);
    pp += __shfl_xor_sync(~0u, pp, 2);
    float s = __shfl_sync(~0u, pp, lane*4);
    if (lane < 8) {
      s *= Prel[(size_t)(l*NRR + r)*NHD + lane] * scale;
      ssc[wid][i][lane] = s;
      mx = fmaxf(mx, s);
    }
  }
  float den = 0.f;
  if (lane < 8) {
    for (int i = 0; i < deg; i++) {
      float ex = expf(ssc[wid][i][lane] - mx);
      ssc[wid][i][lane] = ex;
      den += ex;
    }
  }
  float inv = (lane < 8) ? 1.f/fmaxf(den, 1e-16f) : 0.f;
  float myinv = __shfl_sync(~0u, inv, myh);
  __syncwarp();

  float a0 = 0, a1 = 0, a2 = 0, a3 = 0, a4 = 0, a5 = 0, a6 = 0, a7 = 0;
  for (int i = 0; i < deg; i++) {
    int p = g_elist[off0 + i];
    int r = p >> 16, e = p & 0xFFFF;
    const int* ep = (r == 0) ? e0 : (r == 1) ? e1 : (r == 2) ? e2 : e3;
    int src = ep[e];
    const uint4* mr = (const uint4*)(g_mrelh + (size_t)r*NXH + (size_t)src*HIDDIM);
    float al = ssc[wid][i][myh] * myinv;
    uint4 mv = mr[lane];
    float2 m0 = __half22float2(*(__half2*)&mv.x);
    float2 m1 = __half22float2(*(__half2*)&mv.y);
    float2 m2 = __half22float2(*(__half2*)&mv.z);
    float2 m3 = __half22float2(*(__half2*)&mv.w);
    a0 += al*m0.x; a1 += al*m0.y; a2 += al*m1.x; a3 += al*m1.y;
    a4 += al*m2.x; a5 += al*m2.y; a6 += al*m3.x; a7 += al*m3.y;
  }
  float4* outr = (float4*)(g_agg + (size_t)t*NXH + (size_t)node*HIDDIM);
  float4 o0, o1;
  o0.x = gelu_t(a0); o0.y = gelu_t(a1); o0.z = gelu_t(a2); o0.w = gelu_t(a3);
  o1.x = gelu_t(a4); o1.y = gelu_t(a5); o1.z = gelu_t(a6); o1.w = gelu_t(a7);
  outr[2*lane] = o0; outr[2*lane + 1] = o1;
}

// ================= host orchestration =================
static inline GemmJob JB(const float* Aext, int Aid, long long Aoff, int widx,
                         const float* Bext, int Bid, long long Boff,
                         float* Cext, int Cid, long long Coff,
                         __half* Ch, int mode, int wi, int t) {
  GemmJob j; j.Aext=Aext; j.Aid=Aid; j.Aoff=Aoff; j.widx=widx;
  j.Bext=Bext; j.Bid=Bid; j.Boff=Boff; j.Cext=Cext; j.Cid=Cid; j.Coff=Coff;
  j.Ch=Ch; j.mode=mode; j.wi=wi; j.t=t;
  return j;
}

extern "C" void kernel_launch(void* const* d_in, const int* in_sizes, int n_in,
                              void* d_out, int out_size) {
  const float* x[NT]  = {(const float*)d_in[0], (const float*)d_in[1], (const float*)d_in[2]};
  const int* e0 = (const int*)d_in[3];
  const int* e1 = (const int*)d_in[4];
  const int* e2 = (const int*)d_in[5];
  const int* e3 = (const int*)d_in[6];
  const float* Win   = (const float*)d_in[7];
  const float* b_in  = (const float*)d_in[8];
  const float* Kw    = (const float*)d_in[9];
  const float* Kb    = (const float*)d_in[10];
  const float* Qw    = (const float*)d_in[11];
  const float* Qb    = (const float*)d_in[12];
  const float* Vw    = (const float*)d_in[13];
  const float* Vb    = (const float*)d_in[14];
  const float* Arel  = (const float*)d_in[15];
  const float* Mrel  = (const float*)d_in[16];
  const float* Prel  = (const float*)d_in[17];
  const float* Aw    = (const float*)d_in[18];
  const float* Ab    = (const float*)d_in[19];
  const float* skip  = (const float*)d_in[20];
  const float* ln_g  = (const float*)d_in[21];
  const float* ln_b  = (const float*)d_in[22];
  const float* Wout  = (const float*)d_in[23];
  const float* b_out = (const float*)d_in[24];
  float* out = (float*)d_out;

  static const int RSRC[NRR] = {1, 0, 2, 0};

  __half* krelh = nullptr; __half* mrelh = nullptr;
  cudaGetSymbolAddress((void**)&krelh, g_krelh);
  cudaGetSymbolAddress((void**)&mrelh, g_mrelh);

  cudaFuncSetAttribute(gemm_h, cudaFuncAttributeMaxDynamicSharedMemorySize, GEMM_SMEM);

  fold_weights<<<32, 256>>>(Kw, Kb, Vw, Vb, Arel, Mrel);
  conv_weights<<<dim3(64, NMATS), 256>>>(Win, Qw, Aw, Wout);

  csr_zero<<<TOTSEG/256, 256>>>();
  csr_count<<<TOTEDGE/256, 256>>>(e0, e1, e2, e3);
  csr_scan1<<<TOTSEG/256, 256>>>();
  csr_scan2<<<1, 256>>>();
  csr_scan3<<<TOTSEG/256, 256>>>();
  csr_fill<<<TOTEDGE/256, 256>>>(e0, e1, e2, e3);

  // input projections
  {
    GemmBatch b = {};
    for (int t = 0; t < NT; t++)
      b.j[t] = JB(x[t], -1, 0, t, b_in + t*HIDDIM, -1, 0,
                  nullptr, ID_H, (long long)t*NXH, nullptr, 0, 0, 0);
    gemm_h<<<dim3(256, 3), 256, GEMM_SMEM>>>(b, ln_g, ln_b, skip);
  }

  for (int l = 0; l < NLL; l++) {
    // Q (3, fp32 out) + Krel (4, fp16 out) + Vrel (4, fp16 out)
    {
      GemmBatch b = {};
      int n = 0;
      for (int t = 0; t < NT; t++) {
        int wi = l*NT + t;
        b.j[n++] = JB(nullptr, ID_H, (long long)t*NXH, 3 + wi, Qb + (size_t)wi*HIDDIM, -1, 0,
                      nullptr, ID_Q, (long long)t*NXH, nullptr, 0, 0, 0);
      }
      for (int r = 0; r < NRR; r++) {
        int fo = l*NRR + r;
        b.j[n++] = JB(nullptr, ID_H, (long long)RSRC[r]*NXH, 15 + fo,
                      nullptr, ID_BF, (long long)fo*HIDDIM,
                      nullptr, -1, 0, krelh + (size_t)r*NXH, 2, 0, 0);
      }
      for (int r = 0; r < NRR; r++) {
        int fo = l*NRR + r;
        b.j[n++] = JB(nullptr, ID_H, (long long)RSRC[r]*NXH, 31 + fo,
                      nullptr, ID_BF, (long long)(NLL*NRR + fo)*HIDDIM,
                      nullptr, -1, 0, mrelh + (size_t)r*NXH, 2, 0, 0);
      }
      gemm_h<<<dim3(256, 11), 256, GEMM_SMEM>>>(b, ln_g, ln_b, skip);
    }
    // fused attention
    attn_fused<<<dim3(NN/8, NT), 256>>>(e0, e1, e2, e3, Prel, l);
    // A-linear + gated skip + residual + LN
    {
      GemmBatch b = {};
      for (int t = 0; t < NT; t++) {
        int wi = l*NT + t;
        b.j[t] = JB(nullptr, ID_AGG, (long long)t*NXH, 47 + wi, Ab + (size_t)wi*HIDDIM, -1, 0,
                    nullptr, -1, 0, nullptr, 1, wi, t);
      }
      gemm_h<<<dim3(256, 3), 256, GEMM_SMEM>>>(b, ln_g, ln_b, skip);
    }
  }

  // output projections
  {
    GemmBatch b = {};
    for (int t = 0; t < NT; t++)
      b.j[t] = JB(nullptr, ID_H, (long long)t*NXH, 59 + t, b_out + t*HIDDIM, -1, 0,
                  out + (size_t)t*NXH, -1, 0, nullptr, 0, 0, 0);
    gemm_h<<<dim3(256, 3), 256, GEMM_SMEM>>>(b, ln_g, ln_b, skip);
  }
}